// round 4
// baseline (speedup 1.0000x reference)
#include <cuda_runtime.h>
#include <math_constants.h>

// Problem constants (fixed shapes)
#define BATCH 8
#define LSEQ 4096
#define DDIM 1024
#define SMEM_ROWS 256      // S
#define NG 3               // ngram order
#define M_TOTAL (BATCH*LSEQ)   // 32768

// GEMM tiling
#define BM 128
#define BN 64
#define KT 16
#define NTHREADS 256

// Scratch (no cudaMalloc allowed)
__device__ int g_best[M_TOTAL * NG];   // argmax s per (row, n)
__device__ int g_pad_best[NG];         // argmax_s pos_bias[s,n] for zero-padded rows

// Packed f32x2 FMA (sm_100+): both lanes rounded exactly like scalar fmaf.
__device__ __forceinline__ unsigned long long fma2(unsigned long long a,
                                                   unsigned long long b,
                                                   unsigned long long c) {
    unsigned long long d;
    asm("fma.rn.f32x2 %0, %1, %2, %3;" : "=l"(d) : "l"(a), "l"(b), "l"(c));
    return d;
}

union F4U { float4 f; unsigned long long u[2]; };

__device__ __forceinline__ float lane_lo(unsigned long long v) {
    return __uint_as_float((unsigned int)(v & 0xffffffffull));
}
__device__ __forceinline__ float lane_hi(unsigned long long v) {
    return __uint_as_float((unsigned int)(v >> 32));
}

// ---------------------------------------------------------------------------
// Kernel C: argmax of pos_bias per n (for t < 0 rows, where the ngram is zero)
// ---------------------------------------------------------------------------
__global__ void pad_best_kernel(const float* __restrict__ pb) {
    int n = threadIdx.x;
    if (n < NG) {
        float bv = -CUDART_INF_F; int bi = 0;
        for (int s = 0; s < SMEM_ROWS; s++) {
            float v = pb[s * NG + n];
            if (v > bv) { bv = v; bi = s; }
        }
        g_pad_best[n] = bi;
    }
}

// ---------------------------------------------------------------------------
// Kernel A: fused scores-GEMM + per-row argmax over s, for one n per blockIdx.y
//   scores[m, s] = dot(x[m,:], memory[s, n, :]) + pos_bias[s, n]
//   g_best[m*3+n] = argmax_s scores[m, s]   (ties -> lowest s, like jnp.argmax)
// Inner product uses packed fma.rn.f32x2 (2 FMAs per issue slot) with the
// SAME per-lane k-order as the scalar version -> bitwise-identical scores.
// ---------------------------------------------------------------------------
__global__ __launch_bounds__(NTHREADS)
void score_argmax_kernel(const float* __restrict__ x,
                         const float* __restrict__ mem,
                         const float* __restrict__ pb)
{
    __shared__ float As[KT][BM];        // 8 KB   (transposed: [k][row])
    __shared__ float Bs[KT][BN * 2];    // 8 KB   (duplicated: [k][2c]==[k][2c+1])
    __shared__ float biasSm[BN];
    __shared__ float bestVal[BM];
    __shared__ int   bestIdx[BM];

    const int tid = threadIdx.x;
    const int tx = tid & 15;            // 16 col-threads (4 cols each)
    const int ty = tid >> 4;            // 16 row-threads (8 rows each)
    const int m0 = blockIdx.x * BM;
    const int n  = blockIdx.y;

    if (tid < BM) { bestVal[tid] = -CUDART_INF_F; bestIdx[tid] = 0; }
    __syncthreads();

    // 4 column tiles of 64 cover all S=256 memory rows for this n
    for (int ct = 0; ct < SMEM_ROWS / BN; ct++) {
        const int s_base = ct * BN;

        if (tid < BN) biasSm[tid] = pb[(s_base + tid) * NG + n];

        // Accumulators: acc[i2][j] packs rows (2*i2, 2*i2+1) for column j.
        unsigned long long acc[4][4];
        #pragma unroll
        for (int i = 0; i < 4; i++)
            #pragma unroll
            for (int j = 0; j < 4; j++)
                acc[i][j] = 0ull;

        for (int k0 = 0; k0 < DDIM; k0 += KT) {
            // Load A tile: 128x16 floats = 512 float4, 2 per thread
            #pragma unroll
            for (int t = 0; t < 2; t++) {
                int lid = tid + t * NTHREADS;    // 0..511
                int row = lid >> 2;
                int kc  = lid & 3;
                float4 v = *reinterpret_cast<const float4*>(
                    x + (size_t)(m0 + row) * DDIM + k0 + kc * 4);
                As[kc * 4 + 0][row] = v.x;
                As[kc * 4 + 1][row] = v.y;
                As[kc * 4 + 2][row] = v.z;
                As[kc * 4 + 3][row] = v.w;
            }
            // Load B tile (duplicated): 64x16 floats = 256 float4, 1 per thread
            {
                int col = tid >> 2;
                int kc  = tid & 3;
                int srow = (s_base + col) * NG + n;   // memory[s][n] row
                float4 v = *reinterpret_cast<const float4*>(
                    mem + (size_t)srow * DDIM + k0 + kc * 4);
                *reinterpret_cast<float2*>(&Bs[kc * 4 + 0][2 * col]) = make_float2(v.x, v.x);
                *reinterpret_cast<float2*>(&Bs[kc * 4 + 1][2 * col]) = make_float2(v.y, v.y);
                *reinterpret_cast<float2*>(&Bs[kc * 4 + 2][2 * col]) = make_float2(v.z, v.z);
                *reinterpret_cast<float2*>(&Bs[kc * 4 + 3][2 * col]) = make_float2(v.w, v.w);
            }
            __syncthreads();

            #pragma unroll
            for (int k = 0; k < KT; k++) {
                F4U a0, a1, b0, b1;
                a0.f = *reinterpret_cast<float4*>(&As[k][ty * 8 + 0]);
                a1.f = *reinterpret_cast<float4*>(&As[k][ty * 8 + 4]);
                b0.f = *reinterpret_cast<float4*>(&Bs[k][tx * 8 + 0]);
                b1.f = *reinterpret_cast<float4*>(&Bs[k][tx * 8 + 4]);
                unsigned long long ap[4] = {a0.u[0], a0.u[1], a1.u[0], a1.u[1]};
                unsigned long long bd[4] = {b0.u[0], b0.u[1], b1.u[0], b1.u[1]};
                #pragma unroll
                for (int i = 0; i < 4; i++)
                    #pragma unroll
                    for (int j = 0; j < 4; j++)
                        acc[i][j] = fma2(ap[i], bd[j], acc[i][j]);
            }
            __syncthreads();
        }

        // Per-row argmax over this 64-column tile, merged into running best.
        #pragma unroll
        for (int r = 0; r < 8; r++) {
            int i2 = r >> 1;
            int h  = r & 1;
            int row = ty * 8 + r;
            float v  = (h ? lane_hi(acc[i2][0]) : lane_lo(acc[i2][0])) + biasSm[tx * 4 + 0];
            int  idx = s_base + tx * 4 + 0;
            #pragma unroll
            for (int j = 1; j < 4; j++) {
                float v2 = (h ? lane_hi(acc[i2][j]) : lane_lo(acc[i2][j])) + biasSm[tx * 4 + j];
                int   i2x = s_base + tx * 4 + j;
                if (v2 > v) { v = v2; idx = i2x; }   // strict > keeps lowest idx on tie
            }
            // Reduce across the 16 tx lanes
            #pragma unroll
            for (int off = 1; off < 16; off <<= 1) {
                float v2 = __shfl_xor_sync(0xffffffffu, v, off);
                int   i2x = __shfl_xor_sync(0xffffffffu, idx, off);
                if (v2 > v || (v2 == v && i2x < idx)) { v = v2; idx = i2x; }
            }
            if (tx == 0) {
                if (v > bestVal[row] || (v == bestVal[row] && idx < bestIdx[row])) {
                    bestVal[row] = v; bestIdx[row] = idx;
                }
            }
        }
        __syncthreads();   // protect biasSm/As/Bs reuse + bestVal visibility
    }

    if (tid < BM) {
        g_best[(size_t)(m0 + tid) * NG + n] = bestIdx[tid];
    }
}

// ---------------------------------------------------------------------------
// Kernel B: gather + sum
//   out[b,l,:] = sum_n memory[best_n(b, l+n-2), n, :]   (pad best for t<0)
// One block per output row, one float4 per thread.
// ---------------------------------------------------------------------------
__global__ __launch_bounds__(256)
void gather_kernel(const float* __restrict__ mem,
                   float* __restrict__ out)
{
    int m = blockIdx.x;                // 0..32767 (= b*LSEQ + l)
    int l = m & (LSEQ - 1);
    int d = threadIdx.x;               // 256 threads = 256 float4 = 1024 floats

    int i0 = (l - 2 < 0) ? g_pad_best[0] : g_best[(size_t)(m - 2) * NG + 0];
    int i1 = (l - 1 < 0) ? g_pad_best[1] : g_best[(size_t)(m - 1) * NG + 1];
    int i2 = g_best[(size_t)m * NG + 2];

    const float4* r0 = reinterpret_cast<const float4*>(mem + ((size_t)i0 * NG + 0) * DDIM);
    const float4* r1 = reinterpret_cast<const float4*>(mem + ((size_t)i1 * NG + 1) * DDIM);
    const float4* r2 = reinterpret_cast<const float4*>(mem + ((size_t)i2 * NG + 2) * DDIM);
    float4* o = reinterpret_cast<float4*>(out + (size_t)m * DDIM);

    float4 a = r0[d], b = r1[d], c = r2[d];
    float4 s;
    s.x = (a.x + b.x) + c.x;   // same order as jnp sum over n
    s.y = (a.y + b.y) + c.y;
    s.z = (a.z + b.z) + c.z;
    s.w = (a.w + b.w) + c.w;
    o[d] = s;
}

// ---------------------------------------------------------------------------
extern "C" void kernel_launch(void* const* d_in, const int* in_sizes, int n_in,
                              void* d_out, int out_size)
{
    const float* x   = (const float*)d_in[0];   // (8, 4096, 1024) f32
    const float* mem = (const float*)d_in[1];   // (256, 3, 1024) f32
    const float* pb  = (const float*)d_in[2];   // (256, 3) f32
    float* out = (float*)d_out;                 // (8, 4096, 1024) f32

    pad_best_kernel<<<1, 32>>>(pb);

    dim3 grid(M_TOTAL / BM, NG);
    score_argmax_kernel<<<grid, NTHREADS>>>(x, mem, pb);

    gather_kernel<<<M_TOTAL, 256>>>(mem, out);
}

// round 9
// speedup vs baseline: 6.0345x; 6.0345x over previous
#include <cuda_runtime.h>
#include <cuda_bf16.h>
#include <math_constants.h>
#include <cstdint>

// Problem constants (fixed shapes)
#define BATCH 8
#define LSEQ 4096
#define DDIM 1024
#define SMEM_ROWS 256      // S
#define NG 3               // ngram order
#define M_TOTAL (BATCH*LSEQ)   // 32768
#define NROWS (M_TOTAL*NG)     // 98304 (m,n) rows

// GEMM tiling (mma.sync bf16, family-compatible PTX)
#define TILE_M 128
#define TILE_N 128          // half of S per block
#define KSTAGE 32           // bf16 k per stage (64 B rows)
#define NK (DDIM / KSTAGE)  // 32 k-stages
#define STAGES 3
#define STAGE_A_BYTES (TILE_M * KSTAGE * 2)   // 8192
#define STAGE_BYTES (2 * STAGE_A_BYTES)        // 16384 (A + B)
#define SMEM_DYN (STAGES * STAGE_BYTES)        // 49152

#define MARGIN 2.0f
#define MAXC 8              // candidates per 64-col chunk

// ---------------------------------------------------------------------------
// Scratch (device globals; no cudaMalloc allowed)
// ---------------------------------------------------------------------------
__device__ __align__(128) __nv_bfloat16 g_xbf[(size_t)M_TOTAL * DDIM];      // 64 MB
__device__ __align__(128) __nv_bfloat16 g_membf[(size_t)SMEM_ROWS * NG * DDIM];
__device__ int   g_best[NROWS];
__device__ int   g_pad_best[NG];
__device__ float g_cmax[(size_t)NROWS * 4];        // per-chunk max
__device__ int   g_ccnt[(size_t)NROWS * 4];        // per-chunk candidate count
__device__ int   g_cidx2[(size_t)NROWS * 4 * MAXC];
__device__ float g_csc[(size_t)NROWS * 4 * MAXC];

// ---------------------------------------------------------------------------
// Family-safe PTX helpers (cp.async / ldmatrix / mma.sync only)
// ---------------------------------------------------------------------------
__device__ __forceinline__ uint32_t smem_u32(const void* p) {
    uint32_t a;
    asm("{ .reg .u64 t; cvta.to.shared.u64 t, %1; cvt.u32.u64 %0, t; }" : "=r"(a) : "l"(p));
    return a;
}
__device__ __forceinline__ void cp_async16(uint32_t dst, const void* src) {
    asm volatile("cp.async.cg.shared.global [%0], [%1], 16;" :: "r"(dst), "l"(src));
}
#define CP_COMMIT() asm volatile("cp.async.commit_group;" ::: "memory")
#define CP_WAIT(N)  asm volatile("cp.async.wait_group %0;" :: "n"(N) : "memory")

__device__ __forceinline__ void ldmx4(uint32_t* r, uint32_t addr) {
    asm volatile("ldmatrix.sync.aligned.m8n8.x4.shared.b16 {%0,%1,%2,%3}, [%4];"
                 : "=r"(r[0]), "=r"(r[1]), "=r"(r[2]), "=r"(r[3]) : "r"(addr));
}
__device__ __forceinline__ void mma16816(float* c, const uint32_t* a,
                                         uint32_t b0, uint32_t b1) {
    asm volatile(
        "mma.sync.aligned.m16n8k16.row.col.f32.bf16.bf16.f32 "
        "{%0,%1,%2,%3}, {%4,%5,%6,%7}, {%8,%9}, {%0,%1,%2,%3};"
        : "+f"(c[0]), "+f"(c[1]), "+f"(c[2]), "+f"(c[3])
        : "r"(a[0]), "r"(a[1]), "r"(a[2]), "r"(a[3]), "r"(b0), "r"(b1));
}

// xor swizzle for 64-byte rows: conflict-free ldmatrix across 8-row groups
__device__ __forceinline__ uint32_t swz(int row, int g) {
    return (uint32_t)(row * 64 + ((g ^ ((row >> 1) & 3)) << 4));
}

// ---------------------------------------------------------------------------
// fp32 -> bf16 conversions
// ---------------------------------------------------------------------------
__global__ void cvt_x_kernel(const float4* __restrict__ in, ushort4* __restrict__ out) {
    const int total = M_TOTAL * DDIM / 4;
    for (int i = blockIdx.x * blockDim.x + threadIdx.x; i < total; i += gridDim.x * blockDim.x) {
        float4 v = in[i];
        ushort4 o;
        o.x = __bfloat16_as_ushort(__float2bfloat16(v.x));
        o.y = __bfloat16_as_ushort(__float2bfloat16(v.y));
        o.z = __bfloat16_as_ushort(__float2bfloat16(v.z));
        o.w = __bfloat16_as_ushort(__float2bfloat16(v.w));
        out[i] = o;
    }
}
__global__ void cvt_mem_kernel(const float4* __restrict__ in, ushort4* __restrict__ out) {
    const int total = SMEM_ROWS * NG * DDIM / 4;
    int i = blockIdx.x * blockDim.x + threadIdx.x;
    if (i < total) {
        float4 v = in[i];
        ushort4 o;
        o.x = __bfloat16_as_ushort(__float2bfloat16(v.x));
        o.y = __bfloat16_as_ushort(__float2bfloat16(v.y));
        o.z = __bfloat16_as_ushort(__float2bfloat16(v.z));
        o.w = __bfloat16_as_ushort(__float2bfloat16(v.w));
        out[i] = o;
    }
}

// ---------------------------------------------------------------------------
// pad bias argmax (t<0 rows)
// ---------------------------------------------------------------------------
__global__ void pad_best_kernel(const float* __restrict__ pb) {
    __shared__ float sv[96];
    __shared__ int   si[96];
    int t = threadIdx.x;
    if (t < 96) {
        int n = t % NG, q = t / NG;
        float bv = -CUDART_INF_F; int bi = 0;
        for (int s = q; s < SMEM_ROWS; s += 32) {
            float v = pb[s * NG + n];
            if (v > bv || (v == bv && s < bi)) { bv = v; bi = s; }
        }
        sv[t] = bv; si[t] = bi;
    }
    __syncthreads();
    if (t < NG) {
        float bv = -CUDART_INF_F; int bi = 0;
        for (int j = 0; j < 32; j++) {
            float v = sv[t + j * NG]; int s = si[t + j * NG];
            if (v > bv || (v == bv && s < bi)) { bv = v; bi = s; }
        }
        g_pad_best[t] = bi;
    }
}

// ---------------------------------------------------------------------------
// Score GEMM (bf16 mma.sync, fp32 accum) + fused max/candidate epilogue.
// grid (6, 256): x = half*? -> cx: n = cx>>1, s-half = cx&1; y = m-tile.
// block: 128 threads = 4 warps, tile 128x128, warp tile 64x64.
// ---------------------------------------------------------------------------
__global__ __launch_bounds__(128, 3)
void score_mma_kernel(const float* __restrict__ pb)
{
    extern __shared__ __align__(128) char dynsm[];
    __shared__ float pbias_sm[TILE_N];

    const int tid  = threadIdx.x;
    const int wid  = tid >> 5;
    const int lane = tid & 31;
    const int wm   = wid & 1;          // warp m (0/1): rows 64*wm
    const int wn   = wid >> 1;         // warp n (0/1): cols 64*wn
    const int cx   = blockIdx.x;       // 0..5
    const int n    = cx >> 1;
    const int half = cx & 1;
    const int s0   = half * TILE_N;    // global S offset of this block
    const int m0   = blockIdx.y * TILE_M;

    const uint32_t sbase = smem_u32(dynsm);
    const __nv_bfloat16* __restrict__ xbf = g_xbf;
    const __nv_bfloat16* __restrict__ mbf = g_membf;

    for (int i = tid; i < TILE_N; i += 128)
        pbias_sm[i] = pb[(s0 + i) * NG + n];

    // ---- cp.async stage issue: 1024 x 16B chunks (A 512 + B 512) ----
    auto issue_stage = [&](int st) {
        const int k0 = st * KSTAGE;
        const uint32_t ab = sbase + (st % STAGES) * STAGE_BYTES;
        const uint32_t bb = ab + STAGE_A_BYTES;
        #pragma unroll
        for (int q = 0; q < 8; q++) {
            int c  = tid + q * 128;            // 0..1023
            if (q < 4) {
                int row = c >> 2, g = c & 3;
                cp_async16(ab + swz(row, g),
                           xbf + (size_t)(m0 + row) * DDIM + k0 + g * 8);
            } else {
                int cc = c - 512;
                int row = cc >> 2, g = cc & 3;
                cp_async16(bb + swz(row, g),
                           mbf + ((size_t)(s0 + row) * NG + n) * DDIM + k0 + g * 8);
            }
        }
    };

    issue_stage(0); CP_COMMIT();
    issue_stage(1); CP_COMMIT();
    issue_stage(2); CP_COMMIT();

    float acc[4][8][4];
    #pragma unroll
    for (int i = 0; i < 4; i++)
        #pragma unroll
        for (int j = 0; j < 8; j++)
            #pragma unroll
            for (int c = 0; c < 4; c++) acc[i][j][c] = 0.0f;

    for (int ks = 0; ks < NK; ks++) {
        CP_WAIT(2);
        __syncthreads();

        const uint32_t ab = sbase + (ks % STAGES) * STAGE_BYTES;
        const uint32_t bb = ab + STAGE_A_BYTES;
        #pragma unroll
        for (int t = 0; t < 2; t++) {
            uint32_t ar[4][4];
            #pragma unroll
            for (int i = 0; i < 4; i++)
                ldmx4(ar[i], ab + swz(wm * 64 + i * 16 + (lane & 15),
                                      t * 2 + (lane >> 4)));
            #pragma unroll
            for (int j2 = 0; j2 < 4; j2++) {
                uint32_t br[4];
                ldmx4(br, bb + swz(wn * 64 + j2 * 16 + (lane & 15),
                                   t * 2 + (lane >> 4)));
                #pragma unroll
                for (int i = 0; i < 4; i++) {
                    mma16816(acc[i][2 * j2 + 0], ar[i], br[0], br[2]);
                    mma16816(acc[i][2 * j2 + 1], ar[i], br[1], br[3]);
                }
            }
        }

        __syncthreads();
        if (ks + STAGES < NK) issue_stage(ks + STAGES);
        CP_COMMIT();
    }

    // ---- Epilogue: per-row max + candidates for this warp's 64-col chunk ----
    const int grp = lane >> 2;     // 0..7 row-in-frag
    const int qc  = lane & 3;      // col quad
    const int chunk = half * 2 + wn;
    const unsigned FULL = 0xffffffffu;

    #pragma unroll
    for (int i = 0; i < 4; i++) {
        #pragma unroll
        for (int h = 0; h < 2; h++) {
            const int m = m0 + wm * 64 + i * 16 + h * 8 + grp;
            float vals[16];
            float mx = -CUDART_INF_F;
            #pragma unroll
            for (int j = 0; j < 8; j++) {
                #pragma unroll
                for (int c = 0; c < 2; c++) {
                    int col = wn * 64 + j * 8 + qc * 2 + c;   // local 0..127
                    float v = acc[i][j][h * 2 + c] + pbias_sm[col];
                    vals[j * 2 + c] = v;
                    mx = fmaxf(mx, v);
                }
            }
            mx = fmaxf(mx, __shfl_xor_sync(FULL, mx, 1));
            mx = fmaxf(mx, __shfl_xor_sync(FULL, mx, 2));
            const float thr = mx - MARGIN;

            int   lidx[16]; float lsc[16]; int lc = 0;
            #pragma unroll
            for (int t = 0; t < 16; t++) {
                if (vals[t] > thr) {
                    lidx[lc] = s0 + wn * 64 + (t >> 1) * 8 + qc * 2 + (t & 1);
                    lsc[lc]  = vals[t];
                    lc++;
                }
            }
            int b4 = lane & ~3;
            int c0 = __shfl_sync(FULL, lc, b4 + 0);
            int c1 = __shfl_sync(FULL, lc, b4 + 1);
            int c2 = __shfl_sync(FULL, lc, b4 + 2);
            int c3 = __shfl_sync(FULL, lc, b4 + 3);
            int total = c0 + c1 + c2 + c3;
            int off0  = (qc > 0 ? c0 : 0) + (qc > 1 ? c1 : 0) + (qc > 2 ? c2 : 0);

            size_t ridx = (size_t)m * NG + n;
            size_t cbase = (ridx * 4 + chunk) * MAXC;
            for (int t = 0; t < lc; t++) {
                int p = off0 + t;
                if (p < MAXC) { g_cidx2[cbase + p] = lidx[t]; g_csc[cbase + p] = lsc[t]; }
            }
            if (qc == 0) {
                g_cmax[ridx * 4 + chunk] = mx;
                g_ccnt[ridx * 4 + chunk] = total;
            }
        }
    }
}

// ---------------------------------------------------------------------------
// Exact fp32 dot (sequential k order — matches the validated R1 kernel)
// ---------------------------------------------------------------------------
__device__ __forceinline__ float exact_score(const float4* __restrict__ xr,
                                             const float* __restrict__ mem,
                                             const float* __restrict__ pb,
                                             int s, int n) {
    const float4* mr = reinterpret_cast<const float4*>(mem + ((size_t)s * NG + n) * DDIM);
    float acc = 0.0f;
    #pragma unroll 4
    for (int k = 0; k < DDIM / 4; k++) {
        float4 a = xr[k], b = mr[k];
        acc = fmaf(a.x, b.x, acc);
        acc = fmaf(a.y, b.y, acc);
        acc = fmaf(a.z, b.z, acc);
        acc = fmaf(a.w, b.w, acc);
    }
    return acc + pb[s * NG + n];
}

// ---------------------------------------------------------------------------
// Refine: resolve argmax per (m,n) from chunk maxima + candidates
// ---------------------------------------------------------------------------
__global__ __launch_bounds__(256)
void refine_kernel(const float* __restrict__ x,
                   const float* __restrict__ mem,
                   const float* __restrict__ pb)
{
    int idx = blockIdx.x * blockDim.x + threadIdx.x;
    if (idx >= NROWS) return;
    int m = idx / NG;
    int n = idx - m * NG;

    float gmax = -CUDART_INF_F;
    bool ovf = false;
    int cc[4];
    #pragma unroll
    for (int ch = 0; ch < 4; ch++) {
        float v = g_cmax[(size_t)idx * 4 + ch];
        cc[ch] = g_ccnt[(size_t)idx * 4 + ch];
        if (v > gmax) gmax = v;
        if (cc[ch] > MAXC) ovf = true;
    }
    const float thr = gmax - MARGIN;
    const float4* xr = reinterpret_cast<const float4*>(x + (size_t)m * DDIM);

    if (!ovf) {
        int cand[4 * MAXC]; int nc = 0;
        #pragma unroll
        for (int ch = 0; ch < 4; ch++) {
            size_t cb = ((size_t)idx * 4 + ch) * MAXC;
            for (int p = 0; p < cc[ch]; p++) {
                if (g_csc[cb + p] > thr) cand[nc++] = g_cidx2[cb + p];
            }
        }
        if (nc == 1) { g_best[idx] = cand[0]; return; }
        float bestv = -CUDART_INF_F; int besti = SMEM_ROWS;
        for (int c = 0; c < nc; c++) {
            int s = cand[c];
            float v = exact_score(xr, mem, pb, s, n);
            if (v > bestv || (v == bestv && s < besti)) { bestv = v; besti = s; }
        }
        g_best[idx] = besti;
    } else {
        float bestv = -CUDART_INF_F; int besti = 0;
        for (int s = 0; s < SMEM_ROWS; s++) {
            float v = exact_score(xr, mem, pb, s, n);
            if (v > bestv) { bestv = v; besti = s; }
        }
        g_best[idx] = besti;
    }
}

// ---------------------------------------------------------------------------
// Gather + sum: out[b,l,:] = sum_n memory[best_n(b, l+n-2), n, :]
// ---------------------------------------------------------------------------
__global__ __launch_bounds__(256)
void gather_kernel(const float* __restrict__ mem, float* __restrict__ out)
{
    int m = blockIdx.x;
    int l = m & (LSEQ - 1);
    int d = threadIdx.x;

    int i0 = (l - 2 < 0) ? g_pad_best[0] : g_best[(size_t)(m - 2) * NG + 0];
    int i1 = (l - 1 < 0) ? g_pad_best[1] : g_best[(size_t)(m - 1) * NG + 1];
    int i2 = g_best[(size_t)m * NG + 2];

    const float4* r0 = reinterpret_cast<const float4*>(mem + ((size_t)i0 * NG + 0) * DDIM);
    const float4* r1 = reinterpret_cast<const float4*>(mem + ((size_t)i1 * NG + 1) * DDIM);
    const float4* r2 = reinterpret_cast<const float4*>(mem + ((size_t)i2 * NG + 2) * DDIM);
    float4* o = reinterpret_cast<float4*>(out + (size_t)m * DDIM);

    float4 a = r0[d], b = r1[d], c = r2[d];
    float4 s;
    s.x = (a.x + b.x) + c.x;
    s.y = (a.y + b.y) + c.y;
    s.z = (a.z + b.z) + c.z;
    s.w = (a.w + b.w) + c.w;
    o[d] = s;
}

// ---------------------------------------------------------------------------
extern "C" void kernel_launch(void* const* d_in, const int* in_sizes, int n_in,
                              void* d_out, int out_size)
{
    const float* x   = (const float*)d_in[0];   // (8, 4096, 1024) f32
    const float* mem = (const float*)d_in[1];   // (256, 3, 1024) f32
    const float* pb  = (const float*)d_in[2];   // (256, 3) f32
    float* out = (float*)d_out;                 // (8, 4096, 1024) f32

    void *xbf = nullptr, *mbf = nullptr;
    cudaGetSymbolAddress(&xbf, g_xbf);
    cudaGetSymbolAddress(&mbf, g_membf);

    cudaFuncSetAttribute(score_mma_kernel,
                         cudaFuncAttributeMaxDynamicSharedMemorySize, SMEM_DYN);

    cvt_x_kernel<<<2048, 256>>>((const float4*)x, (ushort4*)xbf);
    cvt_mem_kernel<<<(SMEM_ROWS * NG * DDIM / 4 + 255) / 256, 256>>>(
        (const float4*)mem, (ushort4*)mbf);
    pad_best_kernel<<<1, 96>>>(pb);

    dim3 grid(6, M_TOTAL / TILE_M);   // m-tiles slow => x reuse within a wave
    score_mma_kernel<<<grid, 128, SMEM_DYN>>>(pb);

    refine_kernel<<<(NROWS + 255) / 256, 256>>>(x, mem, pb);
    gather_kernel<<<M_TOTAL, 256>>>(mem, out);
}

// round 12
// speedup vs baseline: 7.3100x; 1.2114x over previous
#include <cuda_runtime.h>
#include <cuda_bf16.h>
#include <math_constants.h>
#include <cstdint>

// Problem constants (fixed shapes)
#define BATCH 8
#define LSEQ 4096
#define DDIM 1024
#define SMEM_ROWS 256      // S
#define NG 3               // ngram order
#define M_TOTAL (BATCH*LSEQ)   // 32768
#define NROWS (M_TOTAL*NG)     // 98304 (m,n) rows

// GEMM tiling (mma.sync bf16, family-compatible PTX)
#define TILE_M 128
#define TILE_N 128          // half of S per block
#define KSTAGE 64           // bf16 k per stage (128 B rows, SW128)
#define NK (DDIM / KSTAGE)  // 16 k-stages
#define STAGES 2
#define STAGE_A_BYTES (TILE_M * KSTAGE * 2)   // 16384
#define STAGE_BYTES (2 * STAGE_A_BYTES)        // 32768 (A + B)
#define SMEM_DYN (STAGES * STAGE_BYTES)        // 65536

#define MARGIN 1.0f
#define MAXC 8              // candidates per 64-col chunk

// ---------------------------------------------------------------------------
// Scratch (device globals; no cudaMalloc allowed)
// ---------------------------------------------------------------------------
__device__ __align__(128) __nv_bfloat16 g_xbf[(size_t)M_TOTAL * DDIM];      // 64 MB
__device__ __align__(128) __nv_bfloat16 g_membf[(size_t)SMEM_ROWS * NG * DDIM];
__device__ int   g_best[NROWS];
__device__ int   g_pad_best[NG];
__device__ float g_cmax[(size_t)NROWS * 4];        // per-chunk max
__device__ int   g_ccnt[(size_t)NROWS * 4];        // per-chunk candidate count
__device__ int   g_cidx2[(size_t)NROWS * 4 * MAXC];
__device__ float g_csc[(size_t)NROWS * 4 * MAXC];

// ---------------------------------------------------------------------------
// Family-safe PTX helpers (cp.async / ldmatrix / mma.sync only)
// ---------------------------------------------------------------------------
__device__ __forceinline__ uint32_t smem_u32(const void* p) {
    uint32_t a;
    asm("{ .reg .u64 t; cvta.to.shared.u64 t, %1; cvt.u32.u64 %0, t; }" : "=r"(a) : "l"(p));
    return a;
}
__device__ __forceinline__ void cp_async16(uint32_t dst, const void* src) {
    asm volatile("cp.async.cg.shared.global [%0], [%1], 16;" :: "r"(dst), "l"(src));
}
#define CP_COMMIT() asm volatile("cp.async.commit_group;" ::: "memory")
#define CP_WAIT(N)  asm volatile("cp.async.wait_group %0;" :: "n"(N) : "memory")

__device__ __forceinline__ void ldmx4(uint32_t* r, uint32_t addr) {
    asm volatile("ldmatrix.sync.aligned.m8n8.x4.shared.b16 {%0,%1,%2,%3}, [%4];"
                 : "=r"(r[0]), "=r"(r[1]), "=r"(r[2]), "=r"(r[3]) : "r"(addr));
}
__device__ __forceinline__ void mma16816(float* c, const uint32_t* a,
                                         uint32_t b0, uint32_t b1) {
    asm volatile(
        "mma.sync.aligned.m16n8k16.row.col.f32.bf16.bf16.f32 "
        "{%0,%1,%2,%3}, {%4,%5,%6,%7}, {%8,%9}, {%0,%1,%2,%3};"
        : "+f"(c[0]), "+f"(c[1]), "+f"(c[2]), "+f"(c[3])
        : "r"(a[0]), "r"(a[1]), "r"(a[2]), "r"(a[3]), "r"(b0), "r"(b1));
}

// SW128 xor swizzle for 128-byte rows: g (16B group 0..7) xored with row&7
__device__ __forceinline__ uint32_t swz128(int row, int g) {
    return (uint32_t)(row * 128 + ((g ^ (row & 7)) << 4));
}

// Pack two floats to bf16x2 (lo = first arg, per __floats2bfloat162_rn contract)
__device__ __forceinline__ uint32_t pack_bf16x2(float lo, float hi) {
    __nv_bfloat162 h = __floats2bfloat162_rn(lo, hi);
    return *reinterpret_cast<uint32_t*>(&h);
}

// ---------------------------------------------------------------------------
// Fused conversions fp32 -> bf16 (x and mem) + pad-bias argmax (block 0 tail)
// ---------------------------------------------------------------------------
#define X_IT8  (M_TOTAL * DDIM / 8)          // 4,194,304 8-float items
#define MEM_IT8 (SMEM_ROWS * NG * DDIM / 8)  //   98,304

__global__ void cvt_all_kernel(const float4* __restrict__ x,
                               const float4* __restrict__ mem,
                               const float* __restrict__ pb)
{
    uint4* xo = reinterpret_cast<uint4*>(g_xbf);
    uint4* mo = reinterpret_cast<uint4*>(g_membf);
    const int total = X_IT8 + MEM_IT8;
    for (int i = blockIdx.x * blockDim.x + threadIdx.x; i < total;
         i += gridDim.x * blockDim.x) {
        const float4* src; uint4* dst; int j;
        if (i < X_IT8) { src = x;  dst = xo; j = i; }
        else           { src = mem; dst = mo; j = i - X_IT8; }
        float4 a = src[2 * j], b = src[2 * j + 1];
        uint4 o;
        o.x = pack_bf16x2(a.x, a.y);
        o.y = pack_bf16x2(a.z, a.w);
        o.z = pack_bf16x2(b.x, b.y);
        o.w = pack_bf16x2(b.z, b.w);
        dst[j] = o;
    }

    // pad-bias argmax, block 0 only (96 working threads, uniform sync)
    if (blockIdx.x == 0) {
        __shared__ float sv[96];
        __shared__ int   si[96];
        int t = threadIdx.x;
        if (t < 96) {
            int n = t % NG, q = t / NG;
            float bv = -CUDART_INF_F; int bi = 0;
            for (int s = q; s < SMEM_ROWS; s += 32) {
                float v = pb[s * NG + n];
                if (v > bv || (v == bv && s < bi)) { bv = v; bi = s; }
            }
            sv[t] = bv; si[t] = bi;
        }
        __syncthreads();
        if (t < NG) {
            float bv = -CUDART_INF_F; int bi = 0;
            for (int j = 0; j < 32; j++) {
                float v = sv[t + j * NG]; int s = si[t + j * NG];
                if (v > bv || (v == bv && s < bi)) { bv = v; bi = s; }
            }
            g_pad_best[t] = bi;
        }
    }
}

// ---------------------------------------------------------------------------
// Score GEMM (bf16 mma.sync, fp32 accum) + fused max/candidate epilogue.
// grid (6, 256): cx -> n = cx>>1, s-half = cx&1; y = m-tile (slow dim => x reuse).
// block: 128 threads = 4 warps, tile 128x128, warp tile 64x64, k-stage 64.
// ---------------------------------------------------------------------------
__global__ __launch_bounds__(128, 3)
void score_mma_kernel(const float* __restrict__ pb)
{
    extern __shared__ __align__(128) char dynsm[];
    __shared__ float pbias_sm[TILE_N];

    const int tid  = threadIdx.x;
    const int wid  = tid >> 5;
    const int lane = tid & 31;
    const int wm   = wid & 1;          // warp m (0/1): rows 64*wm
    const int wn   = wid >> 1;         // warp n (0/1): cols 64*wn
    const int cx   = blockIdx.x;       // 0..5
    const int n    = cx >> 1;
    const int half = cx & 1;
    const int s0   = half * TILE_N;    // global S offset of this block
    const int m0   = blockIdx.y * TILE_M;

    const uint32_t sbase = smem_u32(dynsm);
    const __nv_bfloat16* __restrict__ xbf = g_xbf;
    const __nv_bfloat16* __restrict__ mbf = g_membf;

    for (int i = tid; i < TILE_N; i += 128)
        pbias_sm[i] = pb[(s0 + i) * NG + n];

    // ---- cp.async stage issue: 2048 x 16B chunks (A 1024 + B 1024) ----
    auto issue_stage = [&](int st) {
        const int k0 = st * KSTAGE;
        const uint32_t ab = sbase + (st & 1) * STAGE_BYTES;
        const uint32_t bb = ab + STAGE_A_BYTES;
        #pragma unroll
        for (int q = 0; q < 16; q++) {
            int c = tid + q * 128;              // 0..2047
            if (q < 8) {
                int row = c >> 3, g = c & 7;
                cp_async16(ab + swz128(row, g),
                           xbf + (size_t)(m0 + row) * DDIM + k0 + g * 8);
            } else {
                int cc = c - 1024;
                int row = cc >> 3, g = cc & 7;
                cp_async16(bb + swz128(row, g),
                           mbf + ((size_t)(s0 + row) * NG + n) * DDIM + k0 + g * 8);
            }
        }
    };

    issue_stage(0); CP_COMMIT();
    issue_stage(1); CP_COMMIT();

    float acc[4][8][4];
    #pragma unroll
    for (int i = 0; i < 4; i++)
        #pragma unroll
        for (int j = 0; j < 8; j++)
            #pragma unroll
            for (int c = 0; c < 4; c++) acc[i][j][c] = 0.0f;

    for (int ks = 0; ks < NK; ks++) {
        CP_WAIT(1);
        __syncthreads();

        const uint32_t ab = sbase + (ks & 1) * STAGE_BYTES;
        const uint32_t bb = ab + STAGE_A_BYTES;
        #pragma unroll
        for (int t = 0; t < 4; t++) {          // 4 x k16 within the stage
            uint32_t ar[4][4];
            #pragma unroll
            for (int i = 0; i < 4; i++)
                ldmx4(ar[i], ab + swz128(wm * 64 + i * 16 + (lane & 15),
                                         t * 2 + (lane >> 4)));
            #pragma unroll
            for (int j2 = 0; j2 < 4; j2++) {
                uint32_t br[4];
                ldmx4(br, bb + swz128(wn * 64 + j2 * 16 + (lane & 15),
                                      t * 2 + (lane >> 4)));
                #pragma unroll
                for (int i = 0; i < 4; i++) {
                    mma16816(acc[i][2 * j2 + 0], ar[i], br[0], br[2]);
                    mma16816(acc[i][2 * j2 + 1], ar[i], br[1], br[3]);
                }
            }
        }

        __syncthreads();
        if (ks + STAGES < NK) issue_stage(ks + STAGES);
        CP_COMMIT();
    }

    // ---- Epilogue: per-row max + candidates for this warp's 64-col chunk ----
    const int grp = lane >> 2;     // 0..7 row-in-frag
    const int qc  = lane & 3;      // col quad
    const int chunk = half * 2 + wn;
    const unsigned FULL = 0xffffffffu;

    #pragma unroll
    for (int i = 0; i < 4; i++) {
        #pragma unroll
        for (int h = 0; h < 2; h++) {
            const int m = m0 + wm * 64 + i * 16 + h * 8 + grp;
            float vals[16];
            float mx = -CUDART_INF_F;
            #pragma unroll
            for (int j = 0; j < 8; j++) {
                #pragma unroll
                for (int c = 0; c < 2; c++) {
                    int col = wn * 64 + j * 8 + qc * 2 + c;   // local 0..127
                    float v = acc[i][j][h * 2 + c] + pbias_sm[col];
                    vals[j * 2 + c] = v;
                    mx = fmaxf(mx, v);
                }
            }
            mx = fmaxf(mx, __shfl_xor_sync(FULL, mx, 1));
            mx = fmaxf(mx, __shfl_xor_sync(FULL, mx, 2));
            const float thr = mx - MARGIN;

            int   lidx[16]; float lsc[16]; int lc = 0;
            #pragma unroll
            for (int t = 0; t < 16; t++) {
                if (vals[t] > thr) {
                    lidx[lc] = s0 + wn * 64 + (t >> 1) * 8 + qc * 2 + (t & 1);
                    lsc[lc]  = vals[t];
                    lc++;
                }
            }
            int b4 = lane & ~3;
            int c0 = __shfl_sync(FULL, lc, b4 + 0);
            int c1 = __shfl_sync(FULL, lc, b4 + 1);
            int c2 = __shfl_sync(FULL, lc, b4 + 2);
            int c3 = __shfl_sync(FULL, lc, b4 + 3);
            int total = c0 + c1 + c2 + c3;
            int off0  = (qc > 0 ? c0 : 0) + (qc > 1 ? c1 : 0) + (qc > 2 ? c2 : 0);

            size_t ridx = (size_t)m * NG + n;
            size_t cbase = (ridx * 4 + chunk) * MAXC;
            for (int t = 0; t < lc; t++) {
                int p = off0 + t;
                if (p < MAXC) { g_cidx2[cbase + p] = lidx[t]; g_csc[cbase + p] = lsc[t]; }
            }
            if (qc == 0) {
                g_cmax[ridx * 4 + chunk] = mx;
                g_ccnt[ridx * 4 + chunk] = total;
            }
        }
    }
}

// ---------------------------------------------------------------------------
// Exact fp32 dot (sequential k order — matches the validated R1 kernel)
// ---------------------------------------------------------------------------
__device__ __forceinline__ float exact_score(const float4* __restrict__ xr,
                                             const float* __restrict__ mem,
                                             const float* __restrict__ pb,
                                             int s, int n) {
    const float4* mr = reinterpret_cast<const float4*>(mem + ((size_t)s * NG + n) * DDIM);
    float acc = 0.0f;
    #pragma unroll 4
    for (int k = 0; k < DDIM / 4; k++) {
        float4 a = xr[k], b = mr[k];
        acc = fmaf(a.x, b.x, acc);
        acc = fmaf(a.y, b.y, acc);
        acc = fmaf(a.z, b.z, acc);
        acc = fmaf(a.w, b.w, acc);
    }
    return acc + pb[s * NG + n];
}

// ---------------------------------------------------------------------------
// Refine: resolve argmax per (m,n) from chunk maxima + candidates
// ---------------------------------------------------------------------------
__global__ __launch_bounds__(256)
void refine_kernel(const float* __restrict__ x,
                   const float* __restrict__ mem,
                   const float* __restrict__ pb)
{
    int idx = blockIdx.x * blockDim.x + threadIdx.x;
    if (idx >= NROWS) return;
    int m = idx / NG;
    int n = idx - m * NG;

    float gmax = -CUDART_INF_F;
    bool ovf = false;
    int cc[4];
    #pragma unroll
    for (int ch = 0; ch < 4; ch++) {
        float v = g_cmax[(size_t)idx * 4 + ch];
        cc[ch] = g_ccnt[(size_t)idx * 4 + ch];
        if (v > gmax) gmax = v;
        if (cc[ch] > MAXC) ovf = true;
    }
    const float thr = gmax - MARGIN;
    const float4* xr = reinterpret_cast<const float4*>(x + (size_t)m * DDIM);

    if (!ovf) {
        int cand[4 * MAXC]; int nc = 0;
        #pragma unroll
        for (int ch = 0; ch < 4; ch++) {
            size_t cb = ((size_t)idx * 4 + ch) * MAXC;
            for (int p = 0; p < cc[ch]; p++) {
                if (g_csc[cb + p] > thr) cand[nc++] = g_cidx2[cb + p];
            }
        }
        if (nc == 1) { g_best[idx] = cand[0]; return; }
        float bestv = -CUDART_INF_F; int besti = SMEM_ROWS;
        for (int c = 0; c < nc; c++) {
            int s = cand[c];
            float v = exact_score(xr, mem, pb, s, n);
            if (v > bestv || (v == bestv && s < besti)) { bestv = v; besti = s; }
        }
        g_best[idx] = besti;
    } else {
        float bestv = -CUDART_INF_F; int besti = 0;
        for (int s = 0; s < SMEM_ROWS; s++) {
            float v = exact_score(xr, mem, pb, s, n);
            if (v > bestv) { bestv = v; besti = s; }
        }
        g_best[idx] = besti;
    }
}

// ---------------------------------------------------------------------------
// Gather + sum: out[b,l,:] = sum_n memory[best_n(b, l+n-2), n, :]
// ---------------------------------------------------------------------------
__global__ __launch_bounds__(256)
void gather_kernel(const float* __restrict__ mem, float* __restrict__ out)
{
    int m = blockIdx.x;
    int l = m & (LSEQ - 1);
    int d = threadIdx.x;

    int i0 = (l - 2 < 0) ? g_pad_best[0] : g_best[(size_t)(m - 2) * NG + 0];
    int i1 = (l - 1 < 0) ? g_pad_best[1] : g_best[(size_t)(m - 1) * NG + 1];
    int i2 = g_best[(size_t)m * NG + 2];

    const float4* r0 = reinterpret_cast<const float4*>(mem + ((size_t)i0 * NG + 0) * DDIM);
    const float4* r1 = reinterpret_cast<const float4*>(mem + ((size_t)i1 * NG + 1) * DDIM);
    const float4* r2 = reinterpret_cast<const float4*>(mem + ((size_t)i2 * NG + 2) * DDIM);
    float4* o = reinterpret_cast<float4*>(out + (size_t)m * DDIM);

    float4 a = r0[d], b = r1[d], c = r2[d];
    float4 s;
    s.x = (a.x + b.x) + c.x;
    s.y = (a.y + b.y) + c.y;
    s.z = (a.z + b.z) + c.z;
    s.w = (a.w + b.w) + c.w;
    o[d] = s;
}

// ---------------------------------------------------------------------------
extern "C" void kernel_launch(void* const* d_in, const int* in_sizes, int n_in,
                              void* d_out, int out_size)
{
    const float* x   = (const float*)d_in[0];   // (8, 4096, 1024) f32
    const float* mem = (const float*)d_in[1];   // (256, 3, 1024) f32
    const float* pb  = (const float*)d_in[2];   // (256, 3) f32
    float* out = (float*)d_out;                 // (8, 4096, 1024) f32

    cudaFuncSetAttribute(score_mma_kernel,
                         cudaFuncAttributeMaxDynamicSharedMemorySize, SMEM_DYN);

    cvt_all_kernel<<<2048, 256>>>((const float4*)x, (const float4*)mem, pb);

    dim3 grid(6, M_TOTAL / TILE_M);   // m-tiles slow => x reuse within a wave
    score_mma_kernel<<<grid, 128, SMEM_DYN>>>(pb);

    refine_kernel<<<(NROWS + 255) / 256, 256>>>(x, mem, pb);
    gather_kernel<<<M_TOTAL, 256>>>(mem, out);
}

// round 13
// speedup vs baseline: 8.2943x; 1.1346x over previous
#include <cuda_runtime.h>
#include <cuda_bf16.h>
#include <math_constants.h>
#include <cstdint>

// Problem constants (fixed shapes)
#define BATCH 8
#define LSEQ 4096
#define DDIM 1024
#define SMEM_ROWS 256      // S
#define NG 3               // ngram order
#define M_TOTAL (BATCH*LSEQ)   // 32768
#define NROWS (M_TOTAL*NG)     // 98304 (m,n) rows

// GEMM tiling (mma.sync bf16, family-compatible PTX)
#define TILE_M 128
#define TILE_N 128          // half of S per block
#define KSTAGE 64           // bf16 k per stage (128 B rows, SW128)
#define NK (DDIM / KSTAGE)  // 16 k-stages
#define STAGES 2
#define STAGE_A_BYTES (TILE_M * KSTAGE * 2)   // 16384
#define STAGE_BYTES (2 * STAGE_A_BYTES)        // 32768 (A + B)
#define SMEM_DYN (STAGES * STAGE_BYTES)        // 65536

#define MARGIN 1.0f
#define MAXC 8              // candidates per 64-col chunk
#define PAIR_CAP (1 << 22)  // 4M (row, cand) pairs

// ---------------------------------------------------------------------------
// Scratch (device globals; no cudaMalloc allowed)
// ---------------------------------------------------------------------------
__device__ __align__(128) __nv_bfloat16 g_xbf[(size_t)M_TOTAL * DDIM];      // 64 MB
__device__ __align__(128) __nv_bfloat16 g_membf[(size_t)SMEM_ROWS * NG * DDIM];
__device__ unsigned long long g_bestpack[NROWS];   // (key<<32)|(255-s)
__device__ int   g_pad_best[NG];
__device__ float g_cmax[(size_t)NROWS * 4];        // per-chunk max
__device__ int   g_ccnt[(size_t)NROWS * 4];        // per-chunk candidate count
__device__ int   g_cidx2[(size_t)NROWS * 4 * MAXC];
__device__ float g_csc[(size_t)NROWS * 4 * MAXC];
__device__ int   g_pair_cnt;
__device__ int2  g_pairs[PAIR_CAP];

// ---------------------------------------------------------------------------
// Family-safe PTX helpers (cp.async / ldmatrix / mma.sync only)
// ---------------------------------------------------------------------------
__device__ __forceinline__ uint32_t smem_u32(const void* p) {
    uint32_t a;
    asm("{ .reg .u64 t; cvta.to.shared.u64 t, %1; cvt.u32.u64 %0, t; }" : "=r"(a) : "l"(p));
    return a;
}
__device__ __forceinline__ void cp_async16(uint32_t dst, const void* src) {
    asm volatile("cp.async.cg.shared.global [%0], [%1], 16;" :: "r"(dst), "l"(src));
}
#define CP_COMMIT() asm volatile("cp.async.commit_group;" ::: "memory")
#define CP_WAIT(N)  asm volatile("cp.async.wait_group %0;" :: "n"(N) : "memory")

__device__ __forceinline__ void ldmx4(uint32_t* r, uint32_t addr) {
    asm volatile("ldmatrix.sync.aligned.m8n8.x4.shared.b16 {%0,%1,%2,%3}, [%4];"
                 : "=r"(r[0]), "=r"(r[1]), "=r"(r[2]), "=r"(r[3]) : "r"(addr));
}
__device__ __forceinline__ void mma16816(float* c, const uint32_t* a,
                                         uint32_t b0, uint32_t b1) {
    asm volatile(
        "mma.sync.aligned.m16n8k16.row.col.f32.bf16.bf16.f32 "
        "{%0,%1,%2,%3}, {%4,%5,%6,%7}, {%8,%9}, {%0,%1,%2,%3};"
        : "+f"(c[0]), "+f"(c[1]), "+f"(c[2]), "+f"(c[3])
        : "r"(a[0]), "r"(a[1]), "r"(a[2]), "r"(a[3]), "r"(b0), "r"(b1));
}

// SW128 xor swizzle for 128-byte rows: g (16B group 0..7) xored with row&7
__device__ __forceinline__ uint32_t swz128(int row, int g) {
    return (uint32_t)(row * 128 + ((g ^ (row & 7)) << 4));
}

// Pack two floats to bf16x2 (lo = first arg, per __floats2bfloat162_rn contract)
__device__ __forceinline__ uint32_t pack_bf16x2(float lo, float hi) {
    __nv_bfloat162 h = __floats2bfloat162_rn(lo, hi);
    return *reinterpret_cast<uint32_t*>(&h);
}

// Monotonic float->u32 key (order-preserving for all finite floats)
__device__ __forceinline__ uint32_t fkey(float v) {
    uint32_t u = __float_as_uint(v);
    return (u & 0x80000000u) ? ~u : (u | 0x80000000u);
}
// Winner pack: larger score wins; on equal score, lower s wins (255-s larger)
__device__ __forceinline__ unsigned long long wpack(float v, int s) {
    return ((unsigned long long)fkey(v) << 32) | (unsigned long long)(255 - s);
}
__device__ __forceinline__ int wdecode(unsigned long long p) {
    return 255 - (int)(p & 0xffull);
}

// ---------------------------------------------------------------------------
// Fused conversions fp32 -> bf16 (x and mem) + pad-bias argmax + counter reset
// ---------------------------------------------------------------------------
#define X_IT8  (M_TOTAL * DDIM / 8)          // 4,194,304 8-float items
#define MEM_IT8 (SMEM_ROWS * NG * DDIM / 8)  //   98,304

__global__ void cvt_all_kernel(const float4* __restrict__ x,
                               const float4* __restrict__ mem,
                               const float* __restrict__ pb)
{
    if (blockIdx.x == 0 && threadIdx.x == 0) g_pair_cnt = 0;

    uint4* xo = reinterpret_cast<uint4*>(g_xbf);
    uint4* mo = reinterpret_cast<uint4*>(g_membf);
    const int total = X_IT8 + MEM_IT8;
    for (int i = blockIdx.x * blockDim.x + threadIdx.x; i < total;
         i += gridDim.x * blockDim.x) {
        const float4* src; uint4* dst; int j;
        if (i < X_IT8) { src = x;  dst = xo; j = i; }
        else           { src = mem; dst = mo; j = i - X_IT8; }
        float4 a = src[2 * j], b = src[2 * j + 1];
        uint4 o;
        o.x = pack_bf16x2(a.x, a.y);
        o.y = pack_bf16x2(a.z, a.w);
        o.z = pack_bf16x2(b.x, b.y);
        o.w = pack_bf16x2(b.z, b.w);
        dst[j] = o;
    }

    // pad-bias argmax, block 0 only (96 working threads, uniform sync)
    if (blockIdx.x == 0) {
        __shared__ float sv[96];
        __shared__ int   si[96];
        int t = threadIdx.x;
        if (t < 96) {
            int n = t % NG, q = t / NG;
            float bv = -CUDART_INF_F; int bi = 0;
            for (int s = q; s < SMEM_ROWS; s += 32) {
                float v = pb[s * NG + n];
                if (v > bv || (v == bv && s < bi)) { bv = v; bi = s; }
            }
            sv[t] = bv; si[t] = bi;
        }
        __syncthreads();
        if (t < NG) {
            float bv = -CUDART_INF_F; int bi = 0;
            for (int j = 0; j < 32; j++) {
                float v = sv[t + j * NG]; int s = si[t + j * NG];
                if (v > bv || (v == bv && s < bi)) { bv = v; bi = s; }
            }
            g_pad_best[t] = bi;
        }
    }
}

// ---------------------------------------------------------------------------
// Score GEMM (bf16 mma.sync, fp32 accum) + fused max/candidate epilogue.
// grid (6, 256): cx -> n = cx>>1, s-half = cx&1; y = m-tile (slow dim => x reuse).
// block: 128 threads = 4 warps, tile 128x128, warp tile 64x64, k-stage 64.
// ---------------------------------------------------------------------------
__global__ __launch_bounds__(128, 3)
void score_mma_kernel(const float* __restrict__ pb)
{
    extern __shared__ __align__(128) char dynsm[];
    __shared__ float pbias_sm[TILE_N];

    const int tid  = threadIdx.x;
    const int wid  = tid >> 5;
    const int lane = tid & 31;
    const int wm   = wid & 1;          // warp m (0/1): rows 64*wm
    const int wn   = wid >> 1;         // warp n (0/1): cols 64*wn
    const int cx   = blockIdx.x;       // 0..5
    const int n    = cx >> 1;
    const int half = cx & 1;
    const int s0   = half * TILE_N;    // global S offset of this block
    const int m0   = blockIdx.y * TILE_M;

    const uint32_t sbase = smem_u32(dynsm);
    const __nv_bfloat16* __restrict__ xbf = g_xbf;
    const __nv_bfloat16* __restrict__ mbf = g_membf;

    for (int i = tid; i < TILE_N; i += 128)
        pbias_sm[i] = pb[(s0 + i) * NG + n];

    // ---- cp.async stage issue: 2048 x 16B chunks (A 1024 + B 1024) ----
    auto issue_stage = [&](int st) {
        const int k0 = st * KSTAGE;
        const uint32_t ab = sbase + (st & 1) * STAGE_BYTES;
        const uint32_t bb = ab + STAGE_A_BYTES;
        #pragma unroll
        for (int q = 0; q < 16; q++) {
            int c = tid + q * 128;              // 0..2047
            if (q < 8) {
                int row = c >> 3, g = c & 7;
                cp_async16(ab + swz128(row, g),
                           xbf + (size_t)(m0 + row) * DDIM + k0 + g * 8);
            } else {
                int cc = c - 1024;
                int row = cc >> 3, g = cc & 7;
                cp_async16(bb + swz128(row, g),
                           mbf + ((size_t)(s0 + row) * NG + n) * DDIM + k0 + g * 8);
            }
        }
    };

    issue_stage(0); CP_COMMIT();
    issue_stage(1); CP_COMMIT();

    float acc[4][8][4];
    #pragma unroll
    for (int i = 0; i < 4; i++)
        #pragma unroll
        for (int j = 0; j < 8; j++)
            #pragma unroll
            for (int c = 0; c < 4; c++) acc[i][j][c] = 0.0f;

    for (int ks = 0; ks < NK; ks++) {
        CP_WAIT(1);
        __syncthreads();

        const uint32_t ab = sbase + (ks & 1) * STAGE_BYTES;
        const uint32_t bb = ab + STAGE_A_BYTES;
        #pragma unroll
        for (int t = 0; t < 4; t++) {          // 4 x k16 within the stage
            uint32_t ar[4][4];
            #pragma unroll
            for (int i = 0; i < 4; i++)
                ldmx4(ar[i], ab + swz128(wm * 64 + i * 16 + (lane & 15),
                                         t * 2 + (lane >> 4)));
            #pragma unroll
            for (int j2 = 0; j2 < 4; j2++) {
                uint32_t br[4];
                ldmx4(br, bb + swz128(wn * 64 + j2 * 16 + (lane & 15),
                                      t * 2 + (lane >> 4)));
                #pragma unroll
                for (int i = 0; i < 4; i++) {
                    mma16816(acc[i][2 * j2 + 0], ar[i], br[0], br[2]);
                    mma16816(acc[i][2 * j2 + 1], ar[i], br[1], br[3]);
                }
            }
        }

        __syncthreads();
        if (ks + STAGES < NK) issue_stage(ks + STAGES);
        CP_COMMIT();
    }

    // ---- Epilogue: per-row max + candidates for this warp's 64-col chunk ----
    const int grp = lane >> 2;     // 0..7 row-in-frag
    const int qc  = lane & 3;      // col quad
    const int chunk = half * 2 + wn;
    const unsigned FULL = 0xffffffffu;

    #pragma unroll
    for (int i = 0; i < 4; i++) {
        #pragma unroll
        for (int h = 0; h < 2; h++) {
            const int m = m0 + wm * 64 + i * 16 + h * 8 + grp;
            float vals[16];
            float mx = -CUDART_INF_F;
            #pragma unroll
            for (int j = 0; j < 8; j++) {
                #pragma unroll
                for (int c = 0; c < 2; c++) {
                    int col = wn * 64 + j * 8 + qc * 2 + c;   // local 0..127
                    float v = acc[i][j][h * 2 + c] + pbias_sm[col];
                    vals[j * 2 + c] = v;
                    mx = fmaxf(mx, v);
                }
            }
            mx = fmaxf(mx, __shfl_xor_sync(FULL, mx, 1));
            mx = fmaxf(mx, __shfl_xor_sync(FULL, mx, 2));
            const float thr = mx - MARGIN;

            int   lidx[16]; float lsc[16]; int lc = 0;
            #pragma unroll
            for (int t = 0; t < 16; t++) {
                if (vals[t] > thr) {
                    lidx[lc] = s0 + wn * 64 + (t >> 1) * 8 + qc * 2 + (t & 1);
                    lsc[lc]  = vals[t];
                    lc++;
                }
            }
            int b4 = lane & ~3;
            int c0 = __shfl_sync(FULL, lc, b4 + 0);
            int c1 = __shfl_sync(FULL, lc, b4 + 1);
            int c2 = __shfl_sync(FULL, lc, b4 + 2);
            int c3 = __shfl_sync(FULL, lc, b4 + 3);
            int total = c0 + c1 + c2 + c3;
            int off0  = (qc > 0 ? c0 : 0) + (qc > 1 ? c1 : 0) + (qc > 2 ? c2 : 0);

            size_t ridx = (size_t)m * NG + n;
            size_t cbase = (ridx * 4 + chunk) * MAXC;
            for (int t = 0; t < lc; t++) {
                int p = off0 + t;
                if (p < MAXC) { g_cidx2[cbase + p] = lidx[t]; g_csc[cbase + p] = lsc[t]; }
            }
            if (qc == 0) {
                g_cmax[ridx * 4 + chunk] = mx;
                g_ccnt[ridx * 4 + chunk] = total;
            }
        }
    }
}

// ---------------------------------------------------------------------------
// Exact fp32 dot (sequential k order — matches the validated R1 kernel)
// ---------------------------------------------------------------------------
__device__ __forceinline__ float exact_score(const float4* __restrict__ xr,
                                             const float* __restrict__ mem,
                                             const float* __restrict__ pb,
                                             int s, int n) {
    const float4* mr = reinterpret_cast<const float4*>(mem + ((size_t)s * NG + n) * DDIM);
    float acc = 0.0f;
    #pragma unroll 4
    for (int k = 0; k < DDIM / 4; k++) {
        float4 a = xr[k], b = mr[k];
        acc = fmaf(a.x, b.x, acc);
        acc = fmaf(a.y, b.y, acc);
        acc = fmaf(a.z, b.z, acc);
        acc = fmaf(a.w, b.w, acc);
    }
    return acc + pb[s * NG + n];
}

// ---------------------------------------------------------------------------
// Refine plan: decide nc==1 rows; push (row, cand) pairs for ambiguous rows.
// ---------------------------------------------------------------------------
__global__ __launch_bounds__(256)
void refine_plan_kernel()
{
    int idx = blockIdx.x * blockDim.x + threadIdx.x;
    if (idx >= NROWS) return;

    float gmax = -CUDART_INF_F;
    bool ovf = false;
    int cc[4];
    #pragma unroll
    for (int ch = 0; ch < 4; ch++) {
        float v = g_cmax[(size_t)idx * 4 + ch];
        cc[ch] = g_ccnt[(size_t)idx * 4 + ch];
        if (v > gmax) gmax = v;
        if (cc[ch] > MAXC) ovf = true;
    }
    const float thr = gmax - MARGIN;

    if (!ovf) {
        int cand[4 * MAXC]; int nc = 0;
        #pragma unroll
        for (int ch = 0; ch < 4; ch++) {
            size_t cb = ((size_t)idx * 4 + ch) * MAXC;
            for (int p = 0; p < cc[ch]; p++) {
                if (g_csc[cb + p] > thr) cand[nc++] = g_cidx2[cb + p];
            }
        }
        if (nc == 1) {
            g_bestpack[idx] = wpack(0.0f, cand[0]);   // decided; key irrelevant
            return;
        }
        g_bestpack[idx] = 0ull;
        int base = atomicAdd(&g_pair_cnt, nc);
        for (int c = 0; c < nc; c++) {
            int p = base + c;
            if (p < PAIR_CAP) g_pairs[p] = make_int2(idx, cand[c]);
        }
    } else {
        g_bestpack[idx] = 0ull;
        int base = atomicAdd(&g_pair_cnt, SMEM_ROWS);
        for (int s = 0; s < SMEM_ROWS; s++) {
            int p = base + s;
            if (p < PAIR_CAP) g_pairs[p] = make_int2(idx, s);
        }
    }
}

// ---------------------------------------------------------------------------
// Refine exec: one thread per (row, cand) pair; exact score + atomicMax merge.
// Order-independent combine -> deterministic result.
// ---------------------------------------------------------------------------
__global__ __launch_bounds__(128)
void refine_exec_kernel(const float* __restrict__ x,
                        const float* __restrict__ mem,
                        const float* __restrict__ pb)
{
    int total = g_pair_cnt;
    if (total > PAIR_CAP) total = PAIR_CAP;
    for (int i = blockIdx.x * blockDim.x + threadIdx.x; i < total;
         i += gridDim.x * blockDim.x) {
        int2 pr = g_pairs[i];
        int idx = pr.x, s = pr.y;
        int m = idx / NG;
        int n = idx - m * NG;
        const float4* xr = reinterpret_cast<const float4*>(x + (size_t)m * DDIM);
        float v = exact_score(xr, mem, pb, s, n);
        atomicMax(&g_bestpack[idx], wpack(v, s));
    }
}

// ---------------------------------------------------------------------------
// Gather + sum: out[b,l,:] = sum_n memory[best_n(b, l+n-2), n, :]
// Grid-stride over rows (2048 blocks) for dispatch amortization + MLP.
// ---------------------------------------------------------------------------
__global__ __launch_bounds__(256)
void gather_kernel(const float* __restrict__ mem, float* __restrict__ out)
{
    const int d = threadIdx.x;
    for (int m = blockIdx.x; m < M_TOTAL; m += gridDim.x) {
        int l = m & (LSEQ - 1);

        int i0 = (l - 2 < 0) ? g_pad_best[0] : wdecode(g_bestpack[(size_t)(m - 2) * NG + 0]);
        int i1 = (l - 1 < 0) ? g_pad_best[1] : wdecode(g_bestpack[(size_t)(m - 1) * NG + 1]);
        int i2 = wdecode(g_bestpack[(size_t)m * NG + 2]);

        const float4* r0 = reinterpret_cast<const float4*>(mem + ((size_t)i0 * NG + 0) * DDIM);
        const float4* r1 = reinterpret_cast<const float4*>(mem + ((size_t)i1 * NG + 1) * DDIM);
        const float4* r2 = reinterpret_cast<const float4*>(mem + ((size_t)i2 * NG + 2) * DDIM);
        float4* o = reinterpret_cast<float4*>(out + (size_t)m * DDIM);

        float4 a = r0[d], b = r1[d], c = r2[d];
        float4 s;
        s.x = (a.x + b.x) + c.x;
        s.y = (a.y + b.y) + c.y;
        s.z = (a.z + b.z) + c.z;
        s.w = (a.w + b.w) + c.w;
        o[d] = s;
    }
}

// ---------------------------------------------------------------------------
extern "C" void kernel_launch(void* const* d_in, const int* in_sizes, int n_in,
                              void* d_out, int out_size)
{
    const float* x   = (const float*)d_in[0];   // (8, 4096, 1024) f32
    const float* mem = (const float*)d_in[1];   // (256, 3, 1024) f32
    const float* pb  = (const float*)d_in[2];   // (256, 3) f32
    float* out = (float*)d_out;                 // (8, 4096, 1024) f32

    cudaFuncSetAttribute(score_mma_kernel,
                         cudaFuncAttributeMaxDynamicSharedMemorySize, SMEM_DYN);

    cvt_all_kernel<<<2048, 256>>>((const float4*)x, (const float4*)mem, pb);

    dim3 grid(6, M_TOTAL / TILE_M);   // m-tiles slow => x reuse within a wave
    score_mma_kernel<<<grid, 128, SMEM_DYN>>>(pb);

    refine_plan_kernel<<<(NROWS + 255) / 256, 256>>>();
    refine_exec_kernel<<<2048, 128>>>(x, mem, pb);
    gather_kernel<<<2048, 256>>>(mem, out);
}

// round 14
// speedup vs baseline: 8.8885x; 1.0716x over previous
#include <cuda_runtime.h>
#include <cuda_bf16.h>
#include <math_constants.h>
#include <cstdint>

// Problem constants (fixed shapes)
#define BATCH 8
#define LSEQ 4096
#define DDIM 1024
#define SMEM_ROWS 256      // S
#define NG 3               // ngram order
#define M_TOTAL (BATCH*LSEQ)   // 32768
#define NROWS (M_TOTAL*NG)     // 98304 (m,n) rows

// GEMM tiling (mma.sync bf16, family-compatible PTX)
#define TILE_M 128
#define TILE_N 128          // half of S per block
#define KSTAGE 64           // bf16 k per stage (128 B rows, SW128)
#define NK (DDIM / KSTAGE)  // 16 k-stages
#define STAGES 2
#define STAGE_A_BYTES (TILE_M * KSTAGE * 2)   // 16384
#define STAGE_BYTES (2 * STAGE_A_BYTES)        // 32768 (A + B)
#define SMEM_DYN (STAGES * STAGE_BYTES)        // 65536

#define MARGIN 1.0f
#define MAXC 8              // candidates per 64-col chunk
#define PAIR_CAP (1 << 22)  // 4M (row, cand) pairs

// ---------------------------------------------------------------------------
// Scratch (device globals; no cudaMalloc allowed)
// ---------------------------------------------------------------------------
__device__ __align__(128) __nv_bfloat16 g_xbf[(size_t)M_TOTAL * DDIM];      // 64 MB
__device__ __align__(128) __nv_bfloat16 g_membf[(size_t)SMEM_ROWS * NG * DDIM];
__device__ unsigned long long g_bestpack[NROWS];   // (key<<32)|(255-s)
__device__ int   g_pad_best[NG];
__device__ float g_cmax[(size_t)NROWS * 4];        // per-chunk max
__device__ int   g_ccnt[(size_t)NROWS * 4];        // per-chunk candidate count
__device__ int   g_cidx2[(size_t)NROWS * 4 * MAXC];
__device__ float g_csc[(size_t)NROWS * 4 * MAXC];
__device__ int   g_pair_cnt;
__device__ int2  g_pairs[PAIR_CAP];

// ---------------------------------------------------------------------------
// Family-safe PTX helpers (cp.async / ldmatrix / mma.sync only)
// ---------------------------------------------------------------------------
__device__ __forceinline__ uint32_t smem_u32(const void* p) {
    uint32_t a;
    asm("{ .reg .u64 t; cvta.to.shared.u64 t, %1; cvt.u32.u64 %0, t; }" : "=r"(a) : "l"(p));
    return a;
}
__device__ __forceinline__ void cp_async16(uint32_t dst, const void* src) {
    asm volatile("cp.async.cg.shared.global [%0], [%1], 16;" :: "r"(dst), "l"(src));
}
#define CP_COMMIT() asm volatile("cp.async.commit_group;" ::: "memory")
#define CP_WAIT(N)  asm volatile("cp.async.wait_group %0;" :: "n"(N) : "memory")

__device__ __forceinline__ void ldmx4(uint32_t* r, uint32_t addr) {
    asm volatile("ldmatrix.sync.aligned.m8n8.x4.shared.b16 {%0,%1,%2,%3}, [%4];"
                 : "=r"(r[0]), "=r"(r[1]), "=r"(r[2]), "=r"(r[3]) : "r"(addr));
}
__device__ __forceinline__ void mma16816(float* c, const uint32_t* a,
                                         uint32_t b0, uint32_t b1) {
    asm volatile(
        "mma.sync.aligned.m16n8k16.row.col.f32.bf16.bf16.f32 "
        "{%0,%1,%2,%3}, {%4,%5,%6,%7}, {%8,%9}, {%0,%1,%2,%3};"
        : "+f"(c[0]), "+f"(c[1]), "+f"(c[2]), "+f"(c[3])
        : "r"(a[0]), "r"(a[1]), "r"(a[2]), "r"(a[3]), "r"(b0), "r"(b1));
}

// SW128 xor swizzle for 128-byte rows: g (16B group 0..7) xored with row&7
__device__ __forceinline__ uint32_t swz128(int row, int g) {
    return (uint32_t)(row * 128 + ((g ^ (row & 7)) << 4));
}

// Pack two floats to bf16x2 (lo = first arg, per __floats2bfloat162_rn contract)
__device__ __forceinline__ uint32_t pack_bf16x2(float lo, float hi) {
    __nv_bfloat162 h = __floats2bfloat162_rn(lo, hi);
    return *reinterpret_cast<uint32_t*>(&h);
}

// Monotonic float->u32 key (order-preserving for all finite floats)
__device__ __forceinline__ uint32_t fkey(float v) {
    uint32_t u = __float_as_uint(v);
    return (u & 0x80000000u) ? ~u : (u | 0x80000000u);
}
// Winner pack: larger score wins; on equal score, lower s wins (255-s larger)
__device__ __forceinline__ unsigned long long wpack(float v, int s) {
    return ((unsigned long long)fkey(v) << 32) | (unsigned long long)(255 - s);
}
__device__ __forceinline__ int wdecode(unsigned long long p) {
    return 255 - (int)(p & 0xffull);
}

// ---------------------------------------------------------------------------
// Fused conversions fp32 -> bf16 (x and mem) + pad-bias argmax + counter reset
// ---------------------------------------------------------------------------
#define X_IT8  (M_TOTAL * DDIM / 8)          // 4,194,304 8-float items
#define MEM_IT8 (SMEM_ROWS * NG * DDIM / 8)  //   98,304

__global__ void cvt_all_kernel(const float4* __restrict__ x,
                               const float4* __restrict__ mem,
                               const float* __restrict__ pb)
{
    if (blockIdx.x == 0 && threadIdx.x == 0) g_pair_cnt = 0;

    uint4* xo = reinterpret_cast<uint4*>(g_xbf);
    uint4* mo = reinterpret_cast<uint4*>(g_membf);
    const int total = X_IT8 + MEM_IT8;
    for (int i = blockIdx.x * blockDim.x + threadIdx.x; i < total;
         i += gridDim.x * blockDim.x) {
        const float4* src; uint4* dst; int j;
        if (i < X_IT8) { src = x;  dst = xo; j = i; }
        else           { src = mem; dst = mo; j = i - X_IT8; }
        float4 a = src[2 * j], b = src[2 * j + 1];
        uint4 o;
        o.x = pack_bf16x2(a.x, a.y);
        o.y = pack_bf16x2(a.z, a.w);
        o.z = pack_bf16x2(b.x, b.y);
        o.w = pack_bf16x2(b.z, b.w);
        dst[j] = o;
    }

    // pad-bias argmax, block 0 only (96 working threads, uniform sync)
    if (blockIdx.x == 0) {
        __shared__ float sv[96];
        __shared__ int   si[96];
        int t = threadIdx.x;
        if (t < 96) {
            int n = t % NG, q = t / NG;
            float bv = -CUDART_INF_F; int bi = 0;
            for (int s = q; s < SMEM_ROWS; s += 32) {
                float v = pb[s * NG + n];
                if (v > bv || (v == bv && s < bi)) { bv = v; bi = s; }
            }
            sv[t] = bv; si[t] = bi;
        }
        __syncthreads();
        if (t < NG) {
            float bv = -CUDART_INF_F; int bi = 0;
            for (int j = 0; j < 32; j++) {
                float v = sv[t + j * NG]; int s = si[t + j * NG];
                if (v > bv || (v == bv && s < bi)) { bv = v; bi = s; }
            }
            g_pad_best[t] = bi;
        }
    }
}

// ---------------------------------------------------------------------------
// Score GEMM (bf16 mma.sync, fp32 accum) + fused max/candidate epilogue.
// grid (6, 256): cx -> n = cx>>1, s-half = cx&1; y = m-tile (slow dim => x reuse).
// block: 128 threads = 4 warps, tile 128x128, warp tile 64x64, k-stage 64.
// ---------------------------------------------------------------------------
__global__ __launch_bounds__(128, 3)
void score_mma_kernel(const float* __restrict__ pb)
{
    extern __shared__ __align__(128) char dynsm[];
    __shared__ float pbias_sm[TILE_N];

    const int tid  = threadIdx.x;
    const int wid  = tid >> 5;
    const int lane = tid & 31;
    const int wm   = wid & 1;          // warp m (0/1): rows 64*wm
    const int wn   = wid >> 1;         // warp n (0/1): cols 64*wn
    const int cx   = blockIdx.x;       // 0..5
    const int n    = cx >> 1;
    const int half = cx & 1;
    const int s0   = half * TILE_N;    // global S offset of this block
    const int m0   = blockIdx.y * TILE_M;

    const uint32_t sbase = smem_u32(dynsm);
    const __nv_bfloat16* __restrict__ xbf = g_xbf;
    const __nv_bfloat16* __restrict__ mbf = g_membf;

    for (int i = tid; i < TILE_N; i += 128)
        pbias_sm[i] = pb[(s0 + i) * NG + n];

    // ---- cp.async stage issue: 2048 x 16B chunks (A 1024 + B 1024) ----
    auto issue_stage = [&](int st) {
        const int k0 = st * KSTAGE;
        const uint32_t ab = sbase + (st & 1) * STAGE_BYTES;
        const uint32_t bb = ab + STAGE_A_BYTES;
        #pragma unroll
        for (int q = 0; q < 16; q++) {
            int c = tid + q * 128;              // 0..2047
            if (q < 8) {
                int row = c >> 3, g = c & 7;
                cp_async16(ab + swz128(row, g),
                           xbf + (size_t)(m0 + row) * DDIM + k0 + g * 8);
            } else {
                int cc = c - 1024;
                int row = cc >> 3, g = cc & 7;
                cp_async16(bb + swz128(row, g),
                           mbf + ((size_t)(s0 + row) * NG + n) * DDIM + k0 + g * 8);
            }
        }
    };

    issue_stage(0); CP_COMMIT();
    issue_stage(1); CP_COMMIT();

    float acc[4][8][4];
    #pragma unroll
    for (int i = 0; i < 4; i++)
        #pragma unroll
        for (int j = 0; j < 8; j++)
            #pragma unroll
            for (int c = 0; c < 4; c++) acc[i][j][c] = 0.0f;

    for (int ks = 0; ks < NK; ks++) {
        CP_WAIT(1);
        __syncthreads();

        const uint32_t ab = sbase + (ks & 1) * STAGE_BYTES;
        const uint32_t bb = ab + STAGE_A_BYTES;
        #pragma unroll
        for (int t = 0; t < 4; t++) {          // 4 x k16 within the stage
            uint32_t ar[4][4];
            #pragma unroll
            for (int i = 0; i < 4; i++)
                ldmx4(ar[i], ab + swz128(wm * 64 + i * 16 + (lane & 15),
                                         t * 2 + (lane >> 4)));
            #pragma unroll
            for (int j2 = 0; j2 < 4; j2++) {
                uint32_t br[4];
                ldmx4(br, bb + swz128(wn * 64 + j2 * 16 + (lane & 15),
                                      t * 2 + (lane >> 4)));
                #pragma unroll
                for (int i = 0; i < 4; i++) {
                    mma16816(acc[i][2 * j2 + 0], ar[i], br[0], br[2]);
                    mma16816(acc[i][2 * j2 + 1], ar[i], br[1], br[3]);
                }
            }
        }

        __syncthreads();
        if (ks + STAGES < NK) issue_stage(ks + STAGES);
        CP_COMMIT();
    }

    // ---- Epilogue: per-row max + candidates for this warp's 64-col chunk ----
    const int grp = lane >> 2;     // 0..7 row-in-frag
    const int qc  = lane & 3;      // col quad
    const int chunk = half * 2 + wn;
    const unsigned FULL = 0xffffffffu;

    #pragma unroll
    for (int i = 0; i < 4; i++) {
        #pragma unroll
        for (int h = 0; h < 2; h++) {
            const int m = m0 + wm * 64 + i * 16 + h * 8 + grp;
            float vals[16];
            float mx = -CUDART_INF_F;
            #pragma unroll
            for (int j = 0; j < 8; j++) {
                #pragma unroll
                for (int c = 0; c < 2; c++) {
                    int col = wn * 64 + j * 8 + qc * 2 + c;   // local 0..127
                    float v = acc[i][j][h * 2 + c] + pbias_sm[col];
                    vals[j * 2 + c] = v;
                    mx = fmaxf(mx, v);
                }
            }
            mx = fmaxf(mx, __shfl_xor_sync(FULL, mx, 1));
            mx = fmaxf(mx, __shfl_xor_sync(FULL, mx, 2));
            const float thr = mx - MARGIN;

            int   lidx[16]; float lsc[16]; int lc = 0;
            #pragma unroll
            for (int t = 0; t < 16; t++) {
                if (vals[t] > thr) {
                    lidx[lc] = s0 + wn * 64 + (t >> 1) * 8 + qc * 2 + (t & 1);
                    lsc[lc]  = vals[t];
                    lc++;
                }
            }
            int b4 = lane & ~3;
            int c0 = __shfl_sync(FULL, lc, b4 + 0);
            int c1 = __shfl_sync(FULL, lc, b4 + 1);
            int c2 = __shfl_sync(FULL, lc, b4 + 2);
            int c3 = __shfl_sync(FULL, lc, b4 + 3);
            int total = c0 + c1 + c2 + c3;
            int off0  = (qc > 0 ? c0 : 0) + (qc > 1 ? c1 : 0) + (qc > 2 ? c2 : 0);

            size_t ridx = (size_t)m * NG + n;
            size_t cbase = (ridx * 4 + chunk) * MAXC;
            for (int t = 0; t < lc; t++) {
                int p = off0 + t;
                if (p < MAXC) { g_cidx2[cbase + p] = lidx[t]; g_csc[cbase + p] = lsc[t]; }
            }
            if (qc == 0) {
                g_cmax[ridx * 4 + chunk] = mx;
                g_ccnt[ridx * 4 + chunk] = total;
            }
        }
    }
}

// ---------------------------------------------------------------------------
// Refine plan: decide nc==1 rows; push (row, cand) pairs for ambiguous rows.
// ---------------------------------------------------------------------------
__global__ __launch_bounds__(256)
void refine_plan_kernel()
{
    int idx = blockIdx.x * blockDim.x + threadIdx.x;
    if (idx >= NROWS) return;

    float gmax = -CUDART_INF_F;
    bool ovf = false;
    int cc[4];
    #pragma unroll
    for (int ch = 0; ch < 4; ch++) {
        float v = g_cmax[(size_t)idx * 4 + ch];
        cc[ch] = g_ccnt[(size_t)idx * 4 + ch];
        if (v > gmax) gmax = v;
        if (cc[ch] > MAXC) ovf = true;
    }
    const float thr = gmax - MARGIN;

    if (!ovf) {
        int cand[4 * MAXC]; int nc = 0;
        #pragma unroll
        for (int ch = 0; ch < 4; ch++) {
            size_t cb = ((size_t)idx * 4 + ch) * MAXC;
            for (int p = 0; p < cc[ch]; p++) {
                if (g_csc[cb + p] > thr) cand[nc++] = g_cidx2[cb + p];
            }
        }
        if (nc == 1) {
            g_bestpack[idx] = wpack(0.0f, cand[0]);   // decided; key irrelevant
            return;
        }
        g_bestpack[idx] = 0ull;
        int base = atomicAdd(&g_pair_cnt, nc);
        for (int c = 0; c < nc; c++) {
            int p = base + c;
            if (p < PAIR_CAP) g_pairs[p] = make_int2(idx, cand[c]);
        }
    } else {
        g_bestpack[idx] = 0ull;
        int base = atomicAdd(&g_pair_cnt, SMEM_ROWS);
        for (int s = 0; s < SMEM_ROWS; s++) {
            int p = base + s;
            if (p < PAIR_CAP) g_pairs[p] = make_int2(idx, s);
        }
    }
}

// ---------------------------------------------------------------------------
// Refine exec: one WARP per (row, cand) pair.
// Lane l accumulates elements [32l, 32l+32) sequentially (fixed order), then a
// fixed xor-butterfly reduction combines lanes. Deterministic; fp32 exact.
// Winner merge via order-independent atomicMax keeps lowest-s tie-break.
// ---------------------------------------------------------------------------
__global__ __launch_bounds__(256)
void refine_exec_kernel(const float* __restrict__ x,
                        const float* __restrict__ mem,
                        const float* __restrict__ pb)
{
    const unsigned FULL = 0xffffffffu;
    int total = g_pair_cnt;
    if (total > PAIR_CAP) total = PAIR_CAP;

    const int lane = threadIdx.x & 31;
    const int gw   = (blockIdx.x * blockDim.x + threadIdx.x) >> 5;
    const int nw   = (gridDim.x * blockDim.x) >> 5;

    for (int i = gw; i < total; i += nw) {
        int2 pr = g_pairs[i];
        int idx = pr.x, s = pr.y;
        int m = idx / NG;
        int n = idx - m * NG;

        const float4* xr = reinterpret_cast<const float4*>(x + (size_t)m * DDIM) + lane * 8;
        const float4* mr = reinterpret_cast<const float4*>(mem + ((size_t)s * NG + n) * DDIM) + lane * 8;

        float acc = 0.0f;
        #pragma unroll
        for (int k = 0; k < 8; k++) {
            float4 a = xr[k], b = mr[k];
            acc = fmaf(a.x, b.x, acc);
            acc = fmaf(a.y, b.y, acc);
            acc = fmaf(a.z, b.z, acc);
            acc = fmaf(a.w, b.w, acc);
        }
        #pragma unroll
        for (int off = 16; off >= 1; off >>= 1)
            acc += __shfl_xor_sync(FULL, acc, off);

        if (lane == 0) {
            float v = acc + pb[s * NG + n];
            atomicMax(&g_bestpack[idx], wpack(v, s));
        }
    }
}

// ---------------------------------------------------------------------------
// Gather + sum: out[b,l,:] = sum_n memory[best_n(b, l+n-2), n, :]
// Grid-stride over rows (2048 blocks) for dispatch amortization + MLP.
// ---------------------------------------------------------------------------
__global__ __launch_bounds__(256)
void gather_kernel(const float* __restrict__ mem, float* __restrict__ out)
{
    const int d = threadIdx.x;
    for (int m = blockIdx.x; m < M_TOTAL; m += gridDim.x) {
        int l = m & (LSEQ - 1);

        int i0 = (l - 2 < 0) ? g_pad_best[0] : wdecode(g_bestpack[(size_t)(m - 2) * NG + 0]);
        int i1 = (l - 1 < 0) ? g_pad_best[1] : wdecode(g_bestpack[(size_t)(m - 1) * NG + 1]);
        int i2 = wdecode(g_bestpack[(size_t)m * NG + 2]);

        const float4* r0 = reinterpret_cast<const float4*>(mem + ((size_t)i0 * NG + 0) * DDIM);
        const float4* r1 = reinterpret_cast<const float4*>(mem + ((size_t)i1 * NG + 1) * DDIM);
        const float4* r2 = reinterpret_cast<const float4*>(mem + ((size_t)i2 * NG + 2) * DDIM);
        float4* o = reinterpret_cast<float4*>(out + (size_t)m * DDIM);

        float4 a = r0[d], b = r1[d], c = r2[d];
        float4 s;
        s.x = (a.x + b.x) + c.x;
        s.y = (a.y + b.y) + c.y;
        s.z = (a.z + b.z) + c.z;
        s.w = (a.w + b.w) + c.w;
        o[d] = s;
    }
}

// ---------------------------------------------------------------------------
extern "C" void kernel_launch(void* const* d_in, const int* in_sizes, int n_in,
                              void* d_out, int out_size)
{
    const float* x   = (const float*)d_in[0];   // (8, 4096, 1024) f32
    const float* mem = (const float*)d_in[1];   // (256, 3, 1024) f32
    const float* pb  = (const float*)d_in[2];   // (256, 3) f32
    float* out = (float*)d_out;                 // (8, 4096, 1024) f32

    cudaFuncSetAttribute(score_mma_kernel,
                         cudaFuncAttributeMaxDynamicSharedMemorySize, SMEM_DYN);

    cvt_all_kernel<<<2048, 256>>>((const float4*)x, (const float4*)mem, pb);

    dim3 grid(6, M_TOTAL / TILE_M);   // m-tiles slow => x reuse within a wave
    score_mma_kernel<<<grid, 128, SMEM_DYN>>>(pb);

    refine_plan_kernel<<<(NROWS + 255) / 256, 256>>>();
    refine_exec_kernel<<<1024, 256>>>(x, mem, pb);
    gather_kernel<<<2048, 256>>>(mem, out);
}

// round 15
// speedup vs baseline: 9.3027x; 1.0466x over previous
#include <cuda_runtime.h>
#include <cuda_bf16.h>
#include <math_constants.h>
#include <cstdint>

// Problem constants (fixed shapes)
#define BATCH 8
#define LSEQ 4096
#define DDIM 1024
#define SMEM_ROWS 256      // S
#define NG 3               // ngram order
#define M_TOTAL (BATCH*LSEQ)   // 32768
#define NROWS (M_TOTAL*NG)     // 98304 (m,n) rows

// GEMM tiling (mma.sync bf16, family-compatible PTX)
#define TILE_M 128
#define TILE_N 128          // half of S per block
#define KSTAGE 64           // bf16 k per stage (128 B rows, SW128)
#define NK (DDIM / KSTAGE)  // 16 k-stages
#define STAGES 3
#define STAGE_A_BYTES (TILE_M * KSTAGE * 2)   // 16384
#define STAGE_BYTES (2 * STAGE_A_BYTES)        // 32768 (A + B)
#define SMEM_DYN (STAGES * STAGE_BYTES)        // 98304

#define MARGIN 1.0f
#define MAXC 8              // candidates per 64-col chunk
#define MAXCAND 32          // 4 chunks x MAXC
#define OVF_SENT 255        // slot sentinel: scan 32 s from cand[0]

// ---------------------------------------------------------------------------
// Scratch (device globals; no cudaMalloc allowed)
// ---------------------------------------------------------------------------
__device__ __align__(128) __nv_bfloat16 g_xbf[(size_t)M_TOTAL * DDIM];      // 64 MB
__device__ __align__(128) __nv_bfloat16 g_membf[(size_t)SMEM_ROWS * NG * DDIM];
__device__ unsigned long long g_bestpack[NROWS];   // (key<<32)|(255-s)
__device__ int   g_pad_best[NG];
__device__ float g_cmax[(size_t)NROWS * 4];        // per-chunk max
__device__ int   g_ccnt[(size_t)NROWS * 4];        // per-chunk candidate count
__device__ int   g_cidx2[(size_t)NROWS * 4 * MAXC];
__device__ float g_csc[(size_t)NROWS * 4 * MAXC];
__device__ int   g_row_cnt;
__device__ int   g_rrow[NROWS];                    // ambiguous-row worklist
__device__ int   g_rnc[NROWS];                     // candidate count (or OVF_SENT)
__device__ int   g_rcand[(size_t)NROWS * MAXCAND];

// ---------------------------------------------------------------------------
// Family-safe PTX helpers (cp.async / ldmatrix / mma.sync only)
// ---------------------------------------------------------------------------
__device__ __forceinline__ uint32_t smem_u32(const void* p) {
    uint32_t a;
    asm("{ .reg .u64 t; cvta.to.shared.u64 t, %1; cvt.u32.u64 %0, t; }" : "=r"(a) : "l"(p));
    return a;
}
__device__ __forceinline__ void cp_async16(uint32_t dst, const void* src) {
    asm volatile("cp.async.cg.shared.global [%0], [%1], 16;" :: "r"(dst), "l"(src));
}
#define CP_COMMIT() asm volatile("cp.async.commit_group;" ::: "memory")
#define CP_WAIT(N)  asm volatile("cp.async.wait_group %0;" :: "n"(N) : "memory")

__device__ __forceinline__ void ldmx4(uint32_t* r, uint32_t addr) {
    asm volatile("ldmatrix.sync.aligned.m8n8.x4.shared.b16 {%0,%1,%2,%3}, [%4];"
                 : "=r"(r[0]), "=r"(r[1]), "=r"(r[2]), "=r"(r[3]) : "r"(addr));
}
__device__ __forceinline__ void mma16816(float* c, const uint32_t* a,
                                         uint32_t b0, uint32_t b1) {
    asm volatile(
        "mma.sync.aligned.m16n8k16.row.col.f32.bf16.bf16.f32 "
        "{%0,%1,%2,%3}, {%4,%5,%6,%7}, {%8,%9}, {%0,%1,%2,%3};"
        : "+f"(c[0]), "+f"(c[1]), "+f"(c[2]), "+f"(c[3])
        : "r"(a[0]), "r"(a[1]), "r"(a[2]), "r"(a[3]), "r"(b0), "r"(b1));
}

// SW128 xor swizzle for 128-byte rows: g (16B group 0..7) xored with row&7
__device__ __forceinline__ uint32_t swz128(int row, int g) {
    return (uint32_t)(row * 128 + ((g ^ (row & 7)) << 4));
}

// Pack two floats to bf16x2 (lo = first arg, per __floats2bfloat162_rn contract)
__device__ __forceinline__ uint32_t pack_bf16x2(float lo, float hi) {
    __nv_bfloat162 h = __floats2bfloat162_rn(lo, hi);
    return *reinterpret_cast<uint32_t*>(&h);
}

// Monotonic float->u32 key (order-preserving for all finite floats)
__device__ __forceinline__ uint32_t fkey(float v) {
    uint32_t u = __float_as_uint(v);
    return (u & 0x80000000u) ? ~u : (u | 0x80000000u);
}
// Winner pack: larger score wins; on equal score, lower s wins (255-s larger)
__device__ __forceinline__ unsigned long long wpack(float v, int s) {
    return ((unsigned long long)fkey(v) << 32) | (unsigned long long)(255 - s);
}
__device__ __forceinline__ int wdecode(unsigned long long p) {
    return 255 - (int)(p & 0xffull);
}

// ---------------------------------------------------------------------------
// Fused conversions fp32 -> bf16 (x and mem) + pad-bias argmax + counter reset
// ---------------------------------------------------------------------------
#define X_IT8  (M_TOTAL * DDIM / 8)          // 4,194,304 8-float items
#define MEM_IT8 (SMEM_ROWS * NG * DDIM / 8)  //   98,304

__global__ void cvt_all_kernel(const float4* __restrict__ x,
                               const float4* __restrict__ mem,
                               const float* __restrict__ pb)
{
    if (blockIdx.x == 0 && threadIdx.x == 0) g_row_cnt = 0;

    uint4* xo = reinterpret_cast<uint4*>(g_xbf);
    uint4* mo = reinterpret_cast<uint4*>(g_membf);
    const int total = X_IT8 + MEM_IT8;
    for (int i = blockIdx.x * blockDim.x + threadIdx.x; i < total;
         i += gridDim.x * blockDim.x) {
        const float4* src; uint4* dst; int j;
        if (i < X_IT8) { src = x;  dst = xo; j = i; }
        else           { src = mem; dst = mo; j = i - X_IT8; }
        float4 a = src[2 * j], b = src[2 * j + 1];
        uint4 o;
        o.x = pack_bf16x2(a.x, a.y);
        o.y = pack_bf16x2(a.z, a.w);
        o.z = pack_bf16x2(b.x, b.y);
        o.w = pack_bf16x2(b.z, b.w);
        dst[j] = o;
    }

    // pad-bias argmax, block 0 only (96 working threads, uniform sync)
    if (blockIdx.x == 0) {
        __shared__ float sv[96];
        __shared__ int   si[96];
        int t = threadIdx.x;
        if (t < 96) {
            int n = t % NG, q = t / NG;
            float bv = -CUDART_INF_F; int bi = 0;
            for (int s = q; s < SMEM_ROWS; s += 32) {
                float v = pb[s * NG + n];
                if (v > bv || (v == bv && s < bi)) { bv = v; bi = s; }
            }
            sv[t] = bv; si[t] = bi;
        }
        __syncthreads();
        if (t < NG) {
            float bv = -CUDART_INF_F; int bi = 0;
            for (int j = 0; j < 32; j++) {
                float v = sv[t + j * NG]; int s = si[t + j * NG];
                if (v > bv || (v == bv && s < bi)) { bv = v; bi = s; }
            }
            g_pad_best[t] = bi;
        }
    }
}

// ---------------------------------------------------------------------------
// Score GEMM (bf16 mma.sync, fp32 accum) + fused max/candidate epilogue.
// grid (6, 256): cx -> n = cx>>1, s-half = cx&1; y = m-tile (slow dim => x reuse).
// 3-stage pipeline, ONE sync per k-iter: wait -> sync -> issue ks+2 (into the
// buffer freed at ks-1) -> compute ks.
// ---------------------------------------------------------------------------
__global__ __launch_bounds__(128, 2)
void score_mma_kernel(const float* __restrict__ pb)
{
    extern __shared__ __align__(128) char dynsm[];
    __shared__ float pbias_sm[TILE_N];

    const int tid  = threadIdx.x;
    const int wid  = tid >> 5;
    const int lane = tid & 31;
    const int wm   = wid & 1;          // warp m (0/1): rows 64*wm
    const int wn   = wid >> 1;         // warp n (0/1): cols 64*wn
    const int cx   = blockIdx.x;       // 0..5
    const int n    = cx >> 1;
    const int half = cx & 1;
    const int s0   = half * TILE_N;    // global S offset of this block
    const int m0   = blockIdx.y * TILE_M;

    const uint32_t sbase = smem_u32(dynsm);
    const __nv_bfloat16* __restrict__ xbf = g_xbf;
    const __nv_bfloat16* __restrict__ mbf = g_membf;

    for (int i = tid; i < TILE_N; i += 128)
        pbias_sm[i] = pb[(s0 + i) * NG + n];

    // ---- cp.async stage issue: 2048 x 16B chunks (A 1024 + B 1024) ----
    auto issue_stage = [&](int st) {
        const int k0 = st * KSTAGE;
        const uint32_t ab = sbase + (st % STAGES) * STAGE_BYTES;
        const uint32_t bb = ab + STAGE_A_BYTES;
        #pragma unroll
        for (int q = 0; q < 16; q++) {
            int c = tid + q * 128;              // 0..2047
            if (q < 8) {
                int row = c >> 3, g = c & 7;
                cp_async16(ab + swz128(row, g),
                           xbf + (size_t)(m0 + row) * DDIM + k0 + g * 8);
            } else {
                int cc = c - 1024;
                int row = cc >> 3, g = cc & 7;
                cp_async16(bb + swz128(row, g),
                           mbf + ((size_t)(s0 + row) * NG + n) * DDIM + k0 + g * 8);
            }
        }
    };

    issue_stage(0); CP_COMMIT();
    issue_stage(1); CP_COMMIT();

    float acc[4][8][4];
    #pragma unroll
    for (int i = 0; i < 4; i++)
        #pragma unroll
        for (int j = 0; j < 8; j++)
            #pragma unroll
            for (int c = 0; c < 4; c++) acc[i][j][c] = 0.0f;

    for (int ks = 0; ks < NK; ks++) {
        CP_WAIT(1);            // stage ks complete (only ks+1 may be pending)
        __syncthreads();       // all warps done computing ks-1 -> its buffer free

        if (ks + 2 < NK) issue_stage(ks + 2);   // fills buffer (ks+2)%3 == (ks-1)%3
        CP_COMMIT();

        const uint32_t ab = sbase + (ks % STAGES) * STAGE_BYTES;
        const uint32_t bb = ab + STAGE_A_BYTES;
        #pragma unroll
        for (int t = 0; t < 4; t++) {          // 4 x k16 within the stage
            uint32_t ar[4][4];
            #pragma unroll
            for (int i = 0; i < 4; i++)
                ldmx4(ar[i], ab + swz128(wm * 64 + i * 16 + (lane & 15),
                                         t * 2 + (lane >> 4)));
            #pragma unroll
            for (int j2 = 0; j2 < 4; j2++) {
                uint32_t br[4];
                ldmx4(br, bb + swz128(wn * 64 + j2 * 16 + (lane & 15),
                                      t * 2 + (lane >> 4)));
                #pragma unroll
                for (int i = 0; i < 4; i++) {
                    mma16816(acc[i][2 * j2 + 0], ar[i], br[0], br[2]);
                    mma16816(acc[i][2 * j2 + 1], ar[i], br[1], br[3]);
                }
            }
        }
    }

    // ---- Epilogue: per-row max + candidates for this warp's 64-col chunk ----
    const int grp = lane >> 2;     // 0..7 row-in-frag
    const int qc  = lane & 3;      // col quad
    const int chunk = half * 2 + wn;
    const unsigned FULL = 0xffffffffu;

    #pragma unroll
    for (int i = 0; i < 4; i++) {
        #pragma unroll
        for (int h = 0; h < 2; h++) {
            const int m = m0 + wm * 64 + i * 16 + h * 8 + grp;
            float vals[16];
            float mx = -CUDART_INF_F;
            #pragma unroll
            for (int j = 0; j < 8; j++) {
                #pragma unroll
                for (int c = 0; c < 2; c++) {
                    int col = wn * 64 + j * 8 + qc * 2 + c;   // local 0..127
                    float v = acc[i][j][h * 2 + c] + pbias_sm[col];
                    vals[j * 2 + c] = v;
                    mx = fmaxf(mx, v);
                }
            }
            mx = fmaxf(mx, __shfl_xor_sync(FULL, mx, 1));
            mx = fmaxf(mx, __shfl_xor_sync(FULL, mx, 2));
            const float thr = mx - MARGIN;

            int   lidx[16]; float lsc[16]; int lc = 0;
            #pragma unroll
            for (int t = 0; t < 16; t++) {
                if (vals[t] > thr) {
                    lidx[lc] = s0 + wn * 64 + (t >> 1) * 8 + qc * 2 + (t & 1);
                    lsc[lc]  = vals[t];
                    lc++;
                }
            }
            int b4 = lane & ~3;
            int c0 = __shfl_sync(FULL, lc, b4 + 0);
            int c1 = __shfl_sync(FULL, lc, b4 + 1);
            int c2 = __shfl_sync(FULL, lc, b4 + 2);
            int c3 = __shfl_sync(FULL, lc, b4 + 3);
            int total = c0 + c1 + c2 + c3;
            int off0  = (qc > 0 ? c0 : 0) + (qc > 1 ? c1 : 0) + (qc > 2 ? c2 : 0);

            size_t ridx = (size_t)m * NG + n;
            size_t cbase = (ridx * 4 + chunk) * MAXC;
            for (int t = 0; t < lc; t++) {
                int p = off0 + t;
                if (p < MAXC) { g_cidx2[cbase + p] = lidx[t]; g_csc[cbase + p] = lsc[t]; }
            }
            if (qc == 0) {
                g_cmax[ridx * 4 + chunk] = mx;
                g_ccnt[ridx * 4 + chunk] = total;
            }
        }
    }
}

// ---------------------------------------------------------------------------
// Refine plan: decide nc==1 rows; push one worklist slot per ambiguous row.
// Overflow rows: bestpack=0 + 8 sub-range slots (atomicMax merge in exec).
// ---------------------------------------------------------------------------
__global__ __launch_bounds__(256)
void refine_plan_kernel()
{
    int idx = blockIdx.x * blockDim.x + threadIdx.x;
    if (idx >= NROWS) return;

    float gmax = -CUDART_INF_F;
    bool ovf = false;
    int cc[4];
    #pragma unroll
    for (int ch = 0; ch < 4; ch++) {
        float v = g_cmax[(size_t)idx * 4 + ch];
        cc[ch] = g_ccnt[(size_t)idx * 4 + ch];
        if (v > gmax) gmax = v;
        if (cc[ch] > MAXC) ovf = true;
    }
    const float thr = gmax - MARGIN;

    if (!ovf) {
        int cand[MAXCAND]; int nc = 0;
        #pragma unroll
        for (int ch = 0; ch < 4; ch++) {
            size_t cb = ((size_t)idx * 4 + ch) * MAXC;
            for (int p = 0; p < cc[ch]; p++) {
                if (g_csc[cb + p] > thr) cand[nc++] = g_cidx2[cb + p];
            }
        }
        if (nc == 1) {
            g_bestpack[idx] = wpack(0.0f, cand[0]);   // decided; key irrelevant
            return;
        }
        int slot = atomicAdd(&g_row_cnt, 1);
        g_rrow[slot] = idx;
        g_rnc[slot]  = nc;
        for (int c = 0; c < nc; c++) g_rcand[(size_t)slot * MAXCAND + c] = cand[c];
    } else {
        g_bestpack[idx] = 0ull;     // atomicMax target
        int base = atomicAdd(&g_row_cnt, 8);
        for (int q = 0; q < 8; q++) {
            g_rrow[base + q] = idx;
            g_rnc[base + q]  = OVF_SENT;
            g_rcand[(size_t)(base + q) * MAXCAND] = q * 32;   // s range start
        }
    }
}

// ---------------------------------------------------------------------------
// Refine exec: one WARP per worklist slot. x row loaded to registers ONCE,
// reused across candidates. Dot = lane-blocked fmaf chain + xor-butterfly
// (identical arithmetic to validated R13). Winner: order-independent compare
// (v, then lower s). Normal slots: plain store. OVF sub-slots: atomicMax.
// ---------------------------------------------------------------------------
__global__ __launch_bounds__(256)
void refine_exec_kernel(const float* __restrict__ x,
                        const float* __restrict__ mem,
                        const float* __restrict__ pb)
{
    const unsigned FULL = 0xffffffffu;
    const int total = g_row_cnt;
    const int lane = threadIdx.x & 31;
    const int gw   = (blockIdx.x * blockDim.x + threadIdx.x) >> 5;
    const int nw   = (gridDim.x * blockDim.x) >> 5;

    for (int slot = gw; slot < total; slot += nw) {
        const int idx = g_rrow[slot];
        const int nc  = g_rnc[slot];
        const int m = idx / NG;
        const int n = idx - m * NG;

        // Load this row's x chunk into registers (lane owns 128B = 8 float4)
        const float4* xr = reinterpret_cast<const float4*>(x + (size_t)m * DDIM) + lane * 8;
        float4 ax[8];
        #pragma unroll
        for (int k = 0; k < 8; k++) ax[k] = xr[k];

        const int count = (nc == OVF_SENT) ? 32 : nc;
        const int sbase = (nc == OVF_SENT) ? g_rcand[(size_t)slot * MAXCAND] : 0;

        float bestv = -CUDART_INF_F; int besti = SMEM_ROWS;
        for (int c = 0; c < count; c++) {
            const int s = (nc == OVF_SENT) ? (sbase + c)
                                           : g_rcand[(size_t)slot * MAXCAND + c];
            const float4* mr = reinterpret_cast<const float4*>(
                mem + ((size_t)s * NG + n) * DDIM) + lane * 8;
            float acc = 0.0f;
            #pragma unroll
            for (int k = 0; k < 8; k++) {
                float4 b = mr[k];
                acc = fmaf(ax[k].x, b.x, acc);
                acc = fmaf(ax[k].y, b.y, acc);
                acc = fmaf(ax[k].z, b.z, acc);
                acc = fmaf(ax[k].w, b.w, acc);
            }
            #pragma unroll
            for (int off = 16; off >= 1; off >>= 1)
                acc += __shfl_xor_sync(FULL, acc, off);

            if (lane == 0) {
                float v = acc + pb[s * NG + n];
                if (v > bestv || (v == bestv && s < besti)) { bestv = v; besti = s; }
            }
        }
        if (lane == 0) {
            if (nc == OVF_SENT) atomicMax(&g_bestpack[idx], wpack(bestv, besti));
            else                g_bestpack[idx] = wpack(0.0f, besti);
        }
    }
}

// ---------------------------------------------------------------------------
// Gather + sum: out[b,l,:] = sum_n memory[best_n(b, l+n-2), n, :]
// Grid-stride over rows (2048 blocks) for dispatch amortization + MLP.
// ---------------------------------------------------------------------------
__global__ __launch_bounds__(256)
void gather_kernel(const float* __restrict__ mem, float* __restrict__ out)
{
    const int d = threadIdx.x;
    for (int m = blockIdx.x; m < M_TOTAL; m += gridDim.x) {
        int l = m & (LSEQ - 1);

        int i0 = (l - 2 < 0) ? g_pad_best[0] : wdecode(g_bestpack[(size_t)(m - 2) * NG + 0]);
        int i1 = (l - 1 < 0) ? g_pad_best[1] : wdecode(g_bestpack[(size_t)(m - 1) * NG + 1]);
        int i2 = wdecode(g_bestpack[(size_t)m * NG + 2]);

        const float4* r0 = reinterpret_cast<const float4*>(mem + ((size_t)i0 * NG + 0) * DDIM);
        const float4* r1 = reinterpret_cast<const float4*>(mem + ((size_t)i1 * NG + 1) * DDIM);
        const float4* r2 = reinterpret_cast<const float4*>(mem + ((size_t)i2 * NG + 2) * DDIM);
        float4* o = reinterpret_cast<float4*>(out + (size_t)m * DDIM);

        float4 a = r0[d], b = r1[d], c = r2[d];
        float4 s;
        s.x = (a.x + b.x) + c.x;
        s.y = (a.y + b.y) + c.y;
        s.z = (a.z + b.z) + c.z;
        s.w = (a.w + b.w) + c.w;
        o[d] = s;
    }
}

// ---------------------------------------------------------------------------
extern "C" void kernel_launch(void* const* d_in, const int* in_sizes, int n_in,
                              void* d_out, int out_size)
{
    const float* x   = (const float*)d_in[0];   // (8, 4096, 1024) f32
    const float* mem = (const float*)d_in[1];   // (256, 3, 1024) f32
    const float* pb  = (const float*)d_in[2];   // (256, 3) f32
    float* out = (float*)d_out;                 // (8, 4096, 1024) f32

    cudaFuncSetAttribute(score_mma_kernel,
                         cudaFuncAttributeMaxDynamicSharedMemorySize, SMEM_DYN);

    cvt_all_kernel<<<2048, 256>>>((const float4*)x, (const float4*)mem, pb);

    dim3 grid(6, M_TOTAL / TILE_M);   // m-tiles slow => x reuse within a wave
    score_mma_kernel<<<grid, 128, SMEM_DYN>>>(pb);

    refine_plan_kernel<<<(NROWS + 255) / 256, 256>>>();
    refine_exec_kernel<<<1024, 256>>>(x, mem, pb);
    gather_kernel<<<2048, 256>>>(mem, out);
}

// round 16
// speedup vs baseline: 9.9116x; 1.0655x over previous
#include <cuda_runtime.h>
#include <cuda_bf16.h>
#include <math_constants.h>
#include <cstdint>

// Problem constants (fixed shapes)
#define BATCH 8
#define LSEQ 4096
#define DDIM 1024
#define SMEM_ROWS 256      // S
#define NG 3               // ngram order
#define M_TOTAL (BATCH*LSEQ)   // 32768
#define NROWS (M_TOTAL*NG)     // 98304 (m,n) rows

// GEMM tiling (mma.sync bf16, family-compatible PTX)
#define TILE_M 128
#define TILE_N 128          // half of S per block
#define KSTAGE 64           // bf16 k per stage (128 B rows, SW128)
#define NK (DDIM / KSTAGE)  // 16 k-stages
#define STAGES 3
#define STAGE_A_BYTES (TILE_M * KSTAGE * 2)   // 16384
#define STAGE_BYTES (2 * STAGE_A_BYTES)        // 32768 (A + B)
#define SMEM_DYN (STAGES * STAGE_BYTES)        // 98304

#define MARGIN 1.0f
#define MAXC 8              // candidates per 64-col chunk
#define MAXCAND 32          // 4 chunks x MAXC
#define OVF_SENT 255        // slot sentinel: scan 32 s from cand[0]

// ---------------------------------------------------------------------------
// Scratch (device globals; no cudaMalloc allowed)
// ---------------------------------------------------------------------------
__device__ __align__(128) __nv_bfloat16 g_xbf[(size_t)M_TOTAL * DDIM];      // 64 MB
__device__ __align__(128) __nv_bfloat16 g_membf[(size_t)SMEM_ROWS * NG * DDIM];
__device__ unsigned long long g_bestpack[NROWS];   // (key<<32)|(255-s)
__device__ int   g_pad_best[NG];
__device__ float g_cmax[(size_t)NROWS * 4];        // per-chunk max
__device__ int   g_ccnt[(size_t)NROWS * 4];        // per-chunk candidate count
__device__ int   g_cidx2[(size_t)NROWS * 4 * MAXC];
__device__ float g_csc[(size_t)NROWS * 4 * MAXC];
__device__ int   g_row_cnt;
__device__ int   g_rrow[NROWS];                    // ambiguous-row worklist
__device__ int   g_rnc[NROWS];                     // candidate count (or OVF_SENT)
__device__ int   g_rcand[(size_t)NROWS * MAXCAND];

// ---------------------------------------------------------------------------
// Family-safe PTX helpers (cp.async / ldmatrix / mma.sync only)
// ---------------------------------------------------------------------------
__device__ __forceinline__ uint32_t smem_u32(const void* p) {
    uint32_t a;
    asm("{ .reg .u64 t; cvta.to.shared.u64 t, %1; cvt.u32.u64 %0, t; }" : "=r"(a) : "l"(p));
    return a;
}
__device__ __forceinline__ void cp_async16(uint32_t dst, const void* src) {
    asm volatile("cp.async.cg.shared.global [%0], [%1], 16;" :: "r"(dst), "l"(src));
}
#define CP_COMMIT() asm volatile("cp.async.commit_group;" ::: "memory")
#define CP_WAIT(N)  asm volatile("cp.async.wait_group %0;" :: "n"(N) : "memory")

__device__ __forceinline__ void ldmx4(uint32_t* r, uint32_t addr) {
    asm volatile("ldmatrix.sync.aligned.m8n8.x4.shared.b16 {%0,%1,%2,%3}, [%4];"
                 : "=r"(r[0]), "=r"(r[1]), "=r"(r[2]), "=r"(r[3]) : "r"(addr));
}
__device__ __forceinline__ void mma16816(float* c, const uint32_t* a,
                                         uint32_t b0, uint32_t b1) {
    asm volatile(
        "mma.sync.aligned.m16n8k16.row.col.f32.bf16.bf16.f32 "
        "{%0,%1,%2,%3}, {%4,%5,%6,%7}, {%8,%9}, {%0,%1,%2,%3};"
        : "+f"(c[0]), "+f"(c[1]), "+f"(c[2]), "+f"(c[3])
        : "r"(a[0]), "r"(a[1]), "r"(a[2]), "r"(a[3]), "r"(b0), "r"(b1));
}

// SW128 xor swizzle for 128-byte rows: g (16B group 0..7) xored with row&7
__device__ __forceinline__ uint32_t swz128(int row, int g) {
    return (uint32_t)(row * 128 + ((g ^ (row & 7)) << 4));
}

// Pack two floats to bf16x2 (lo = first arg, per __floats2bfloat162_rn contract)
__device__ __forceinline__ uint32_t pack_bf16x2(float lo, float hi) {
    __nv_bfloat162 h = __floats2bfloat162_rn(lo, hi);
    return *reinterpret_cast<uint32_t*>(&h);
}

// Monotonic float->u32 key (order-preserving for all finite floats)
__device__ __forceinline__ uint32_t fkey(float v) {
    uint32_t u = __float_as_uint(v);
    return (u & 0x80000000u) ? ~u : (u | 0x80000000u);
}
// Winner pack: larger score wins; on equal score, lower s wins (255-s larger)
__device__ __forceinline__ unsigned long long wpack(float v, int s) {
    return ((unsigned long long)fkey(v) << 32) | (unsigned long long)(255 - s);
}
__device__ __forceinline__ int wdecode(unsigned long long p) {
    return 255 - (int)(p & 0xffull);
}

// ---------------------------------------------------------------------------
// Fused conversions fp32 -> bf16 (x and mem) + pad-bias argmax + counter reset
// ---------------------------------------------------------------------------
#define X_IT8  (M_TOTAL * DDIM / 8)          // 4,194,304 8-float items
#define MEM_IT8 (SMEM_ROWS * NG * DDIM / 8)  //   98,304

__global__ void cvt_all_kernel(const float4* __restrict__ x,
                               const float4* __restrict__ mem,
                               const float* __restrict__ pb)
{
    if (blockIdx.x == 0 && threadIdx.x == 0) g_row_cnt = 0;

    uint4* xo = reinterpret_cast<uint4*>(g_xbf);
    uint4* mo = reinterpret_cast<uint4*>(g_membf);
    const int total = X_IT8 + MEM_IT8;
    for (int i = blockIdx.x * blockDim.x + threadIdx.x; i < total;
         i += gridDim.x * blockDim.x) {
        const float4* src; uint4* dst; int j;
        if (i < X_IT8) { src = x;  dst = xo; j = i; }
        else           { src = mem; dst = mo; j = i - X_IT8; }
        float4 a = src[2 * j], b = src[2 * j + 1];
        uint4 o;
        o.x = pack_bf16x2(a.x, a.y);
        o.y = pack_bf16x2(a.z, a.w);
        o.z = pack_bf16x2(b.x, b.y);
        o.w = pack_bf16x2(b.z, b.w);
        dst[j] = o;
    }

    // pad-bias argmax, block 0 only (96 working threads, uniform sync)
    if (blockIdx.x == 0) {
        __shared__ float sv[96];
        __shared__ int   si[96];
        int t = threadIdx.x;
        if (t < 96) {
            int n = t % NG, q = t / NG;
            float bv = -CUDART_INF_F; int bi = 0;
            for (int s = q; s < SMEM_ROWS; s += 32) {
                float v = pb[s * NG + n];
                if (v > bv || (v == bv && s < bi)) { bv = v; bi = s; }
            }
            sv[t] = bv; si[t] = bi;
        }
        __syncthreads();
        if (t < NG) {
            float bv = -CUDART_INF_F; int bi = 0;
            for (int j = 0; j < 32; j++) {
                float v = sv[t + j * NG]; int s = si[t + j * NG];
                if (v > bv || (v == bv && s < bi)) { bv = v; bi = s; }
            }
            g_pad_best[t] = bi;
        }
    }
}

// ---------------------------------------------------------------------------
// Score GEMM (bf16 mma.sync, fp32 accum) + fused max/candidate epilogue.
// grid (6, 256): cx -> n = cx>>1, s-half = cx&1; y = m-tile (slow dim => x reuse).
// 3-stage pipeline, ONE sync per k-iter: wait -> sync -> issue ks+2 (into the
// buffer freed at ks-1) -> compute ks.
// ---------------------------------------------------------------------------
__global__ __launch_bounds__(128, 2)
void score_mma_kernel(const float* __restrict__ pb)
{
    extern __shared__ __align__(128) char dynsm[];
    __shared__ float pbias_sm[TILE_N];

    const int tid  = threadIdx.x;
    const int wid  = tid >> 5;
    const int lane = tid & 31;
    const int wm   = wid & 1;          // warp m (0/1): rows 64*wm
    const int wn   = wid >> 1;         // warp n (0/1): cols 64*wn
    const int cx   = blockIdx.x;       // 0..5
    const int n    = cx >> 1;
    const int half = cx & 1;
    const int s0   = half * TILE_N;    // global S offset of this block
    const int m0   = blockIdx.y * TILE_M;

    const uint32_t sbase = smem_u32(dynsm);
    const __nv_bfloat16* __restrict__ xbf = g_xbf;
    const __nv_bfloat16* __restrict__ mbf = g_membf;

    for (int i = tid; i < TILE_N; i += 128)
        pbias_sm[i] = pb[(s0 + i) * NG + n];

    // ---- cp.async stage issue: 2048 x 16B chunks (A 1024 + B 1024) ----
    auto issue_stage = [&](int st) {
        const int k0 = st * KSTAGE;
        const uint32_t ab = sbase + (st % STAGES) * STAGE_BYTES;
        const uint32_t bb = ab + STAGE_A_BYTES;
        #pragma unroll
        for (int q = 0; q < 16; q++) {
            int c = tid + q * 128;              // 0..2047
            if (q < 8) {
                int row = c >> 3, g = c & 7;
                cp_async16(ab + swz128(row, g),
                           xbf + (size_t)(m0 + row) * DDIM + k0 + g * 8);
            } else {
                int cc = c - 1024;
                int row = cc >> 3, g = cc & 7;
                cp_async16(bb + swz128(row, g),
                           mbf + ((size_t)(s0 + row) * NG + n) * DDIM + k0 + g * 8);
            }
        }
    };

    issue_stage(0); CP_COMMIT();
    issue_stage(1); CP_COMMIT();

    float acc[4][8][4];
    #pragma unroll
    for (int i = 0; i < 4; i++)
        #pragma unroll
        for (int j = 0; j < 8; j++)
            #pragma unroll
            for (int c = 0; c < 4; c++) acc[i][j][c] = 0.0f;

    for (int ks = 0; ks < NK; ks++) {
        CP_WAIT(1);            // stage ks complete (only ks+1 may be pending)
        __syncthreads();       // all warps done computing ks-1 -> its buffer free

        if (ks + 2 < NK) issue_stage(ks + 2);   // fills buffer (ks+2)%3 == (ks-1)%3
        CP_COMMIT();

        const uint32_t ab = sbase + (ks % STAGES) * STAGE_BYTES;
        const uint32_t bb = ab + STAGE_A_BYTES;
        #pragma unroll
        for (int t = 0; t < 4; t++) {          // 4 x k16 within the stage
            uint32_t ar[4][4];
            #pragma unroll
            for (int i = 0; i < 4; i++)
                ldmx4(ar[i], ab + swz128(wm * 64 + i * 16 + (lane & 15),
                                         t * 2 + (lane >> 4)));
            #pragma unroll
            for (int j2 = 0; j2 < 4; j2++) {
                uint32_t br[4];
                ldmx4(br, bb + swz128(wn * 64 + j2 * 16 + (lane & 15),
                                      t * 2 + (lane >> 4)));
                #pragma unroll
                for (int i = 0; i < 4; i++) {
                    mma16816(acc[i][2 * j2 + 0], ar[i], br[0], br[2]);
                    mma16816(acc[i][2 * j2 + 1], ar[i], br[1], br[3]);
                }
            }
        }
    }

    // ---- Epilogue: per-row max + candidates for this warp's 64-col chunk ----
    const int grp = lane >> 2;     // 0..7 row-in-frag
    const int qc  = lane & 3;      // col quad
    const int chunk = half * 2 + wn;
    const unsigned FULL = 0xffffffffu;

    #pragma unroll
    for (int i = 0; i < 4; i++) {
        #pragma unroll
        for (int h = 0; h < 2; h++) {
            const int m = m0 + wm * 64 + i * 16 + h * 8 + grp;
            float vals[16];
            float mx = -CUDART_INF_F;
            #pragma unroll
            for (int j = 0; j < 8; j++) {
                #pragma unroll
                for (int c = 0; c < 2; c++) {
                    int col = wn * 64 + j * 8 + qc * 2 + c;   // local 0..127
                    float v = acc[i][j][h * 2 + c] + pbias_sm[col];
                    vals[j * 2 + c] = v;
                    mx = fmaxf(mx, v);
                }
            }
            mx = fmaxf(mx, __shfl_xor_sync(FULL, mx, 1));
            mx = fmaxf(mx, __shfl_xor_sync(FULL, mx, 2));
            const float thr = mx - MARGIN;

            int   lidx[16]; float lsc[16]; int lc = 0;
            #pragma unroll
            for (int t = 0; t < 16; t++) {
                if (vals[t] > thr) {
                    lidx[lc] = s0 + wn * 64 + (t >> 1) * 8 + qc * 2 + (t & 1);
                    lsc[lc]  = vals[t];
                    lc++;
                }
            }
            int b4 = lane & ~3;
            int c0 = __shfl_sync(FULL, lc, b4 + 0);
            int c1 = __shfl_sync(FULL, lc, b4 + 1);
            int c2 = __shfl_sync(FULL, lc, b4 + 2);
            int c3 = __shfl_sync(FULL, lc, b4 + 3);
            int total = c0 + c1 + c2 + c3;
            int off0  = (qc > 0 ? c0 : 0) + (qc > 1 ? c1 : 0) + (qc > 2 ? c2 : 0);

            size_t ridx = (size_t)m * NG + n;
            size_t cbase = (ridx * 4 + chunk) * MAXC;
            for (int t = 0; t < lc; t++) {
                int p = off0 + t;
                if (p < MAXC) { g_cidx2[cbase + p] = lidx[t]; g_csc[cbase + p] = lsc[t]; }
            }
            if (qc == 0) {
                g_cmax[ridx * 4 + chunk] = mx;
                g_ccnt[ridx * 4 + chunk] = total;
            }
        }
    }
}

// ---------------------------------------------------------------------------
// Refine plan: decide nc==1 rows; push one worklist slot per ambiguous row.
// Overflow rows: bestpack=0 + 8 sub-range slots (atomicMax merge in exec).
// ---------------------------------------------------------------------------
__global__ __launch_bounds__(256)
void refine_plan_kernel()
{
    int idx = blockIdx.x * blockDim.x + threadIdx.x;
    if (idx >= NROWS) return;

    float gmax = -CUDART_INF_F;
    bool ovf = false;
    int cc[4];
    #pragma unroll
    for (int ch = 0; ch < 4; ch++) {
        float v = g_cmax[(size_t)idx * 4 + ch];
        cc[ch] = g_ccnt[(size_t)idx * 4 + ch];
        if (v > gmax) gmax = v;
        if (cc[ch] > MAXC) ovf = true;
    }
    const float thr = gmax - MARGIN;

    if (!ovf) {
        int cand[MAXCAND]; int nc = 0;
        #pragma unroll
        for (int ch = 0; ch < 4; ch++) {
            size_t cb = ((size_t)idx * 4 + ch) * MAXC;
            for (int p = 0; p < cc[ch]; p++) {
                if (g_csc[cb + p] > thr) cand[nc++] = g_cidx2[cb + p];
            }
        }
        if (nc == 1) {
            g_bestpack[idx] = wpack(0.0f, cand[0]);   // decided; key irrelevant
            return;
        }
        int slot = atomicAdd(&g_row_cnt, 1);
        g_rrow[slot] = idx;
        g_rnc[slot]  = nc;
        for (int c = 0; c < nc; c++) g_rcand[(size_t)slot * MAXCAND + c] = cand[c];
    } else {
        g_bestpack[idx] = 0ull;     // atomicMax target
        int base = atomicAdd(&g_row_cnt, 8);
        for (int q = 0; q < 8; q++) {
            g_rrow[base + q] = idx;
            g_rnc[base + q]  = OVF_SENT;
            g_rcand[(size_t)(base + q) * MAXCAND] = q * 32;   // s range start
        }
    }
}

// ---------------------------------------------------------------------------
// Refine exec: one WARP per worklist slot. COALESCED lane mapping: lane l owns
// float4 indices l + 32k (k=0..7) -> each LDG.128 covers one contiguous 512B
// span (nL=4) instead of 32 scattered lines (nL=32). x row cached in regs,
// reused across candidates. Exact fp32 dot + xor-butterfly reduction;
// winner via order-independent compare (v, then lower s).
// ---------------------------------------------------------------------------
__global__ __launch_bounds__(256)
void refine_exec_kernel(const float* __restrict__ x,
                        const float* __restrict__ mem,
                        const float* __restrict__ pb)
{
    const unsigned FULL = 0xffffffffu;
    const int total = g_row_cnt;
    const int lane = threadIdx.x & 31;
    const int gw   = (blockIdx.x * blockDim.x + threadIdx.x) >> 5;
    const int nw   = (gridDim.x * blockDim.x) >> 5;

    for (int slot = gw; slot < total; slot += nw) {
        const int idx = g_rrow[slot];
        const int nc  = g_rnc[slot];
        const int m = idx / NG;
        const int n = idx - m * NG;

        // Coalesced x-row load into registers: lane l takes float4 l + 32k
        const float4* xr = reinterpret_cast<const float4*>(x + (size_t)m * DDIM);
        float4 ax[8];
        #pragma unroll
        for (int k = 0; k < 8; k++) ax[k] = xr[lane + 32 * k];

        const int count = (nc == OVF_SENT) ? 32 : nc;
        const int sbase = (nc == OVF_SENT) ? g_rcand[(size_t)slot * MAXCAND] : 0;

        float bestv = -CUDART_INF_F; int besti = SMEM_ROWS;
        for (int c = 0; c < count; c++) {
            const int s = (nc == OVF_SENT) ? (sbase + c)
                                           : g_rcand[(size_t)slot * MAXCAND + c];
            const float4* mr = reinterpret_cast<const float4*>(
                mem + ((size_t)s * NG + n) * DDIM);
            float acc = 0.0f;
            #pragma unroll
            for (int k = 0; k < 8; k++) {
                float4 b = mr[lane + 32 * k];
                acc = fmaf(ax[k].x, b.x, acc);
                acc = fmaf(ax[k].y, b.y, acc);
                acc = fmaf(ax[k].z, b.z, acc);
                acc = fmaf(ax[k].w, b.w, acc);
            }
            #pragma unroll
            for (int off = 16; off >= 1; off >>= 1)
                acc += __shfl_xor_sync(FULL, acc, off);

            if (lane == 0) {
                float v = acc + pb[s * NG + n];
                if (v > bestv || (v == bestv && s < besti)) { bestv = v; besti = s; }
            }
        }
        if (lane == 0) {
            if (nc == OVF_SENT) atomicMax(&g_bestpack[idx], wpack(bestv, besti));
            else                g_bestpack[idx] = wpack(0.0f, besti);
        }
    }
}

// ---------------------------------------------------------------------------
// Gather + sum: out[b,l,:] = sum_n memory[best_n(b, l+n-2), n, :]
// Grid-stride over rows (2048 blocks) for dispatch amortization + MLP.
// ---------------------------------------------------------------------------
__global__ __launch_bounds__(256)
void gather_kernel(const float* __restrict__ mem, float* __restrict__ out)
{
    const int d = threadIdx.x;
    for (int m = blockIdx.x; m < M_TOTAL; m += gridDim.x) {
        int l = m & (LSEQ - 1);

        int i0 = (l - 2 < 0) ? g_pad_best[0] : wdecode(g_bestpack[(size_t)(m - 2) * NG + 0]);
        int i1 = (l - 1 < 0) ? g_pad_best[1] : wdecode(g_bestpack[(size_t)(m - 1) * NG + 1]);
        int i2 = wdecode(g_bestpack[(size_t)m * NG + 2]);

        const float4* r0 = reinterpret_cast<const float4*>(mem + ((size_t)i0 * NG + 0) * DDIM);
        const float4* r1 = reinterpret_cast<const float4*>(mem + ((size_t)i1 * NG + 1) * DDIM);
        const float4* r2 = reinterpret_cast<const float4*>(mem + ((size_t)i2 * NG + 2) * DDIM);
        float4* o = reinterpret_cast<float4*>(out + (size_t)m * DDIM);

        float4 a = r0[d], b = r1[d], c = r2[d];
        float4 s;
        s.x = (a.x + b.x) + c.x;
        s.y = (a.y + b.y) + c.y;
        s.z = (a.z + b.z) + c.z;
        s.w = (a.w + b.w) + c.w;
        o[d] = s;
    }
}

// ---------------------------------------------------------------------------
extern "C" void kernel_launch(void* const* d_in, const int* in_sizes, int n_in,
                              void* d_out, int out_size)
{
    const float* x   = (const float*)d_in[0];   // (8, 4096, 1024) f32
    const float* mem = (const float*)d_in[1];   // (256, 3, 1024) f32
    const float* pb  = (const float*)d_in[2];   // (256, 3) f32
    float* out = (float*)d_out;                 // (8, 4096, 1024) f32

    cudaFuncSetAttribute(score_mma_kernel,
                         cudaFuncAttributeMaxDynamicSharedMemorySize, SMEM_DYN);

    cvt_all_kernel<<<2048, 256>>>((const float4*)x, (const float4*)mem, pb);

    dim3 grid(6, M_TOTAL / TILE_M);   // m-tiles slow => x reuse within a wave
    score_mma_kernel<<<grid, 128, SMEM_DYN>>>(pb);

    refine_plan_kernel<<<(NROWS + 255) / 256, 256>>>();
    refine_exec_kernel<<<1024, 256>>>(x, mem, pb);
    gather_kernel<<<2048, 256>>>(mem, out);
}

// round 17
// speedup vs baseline: 10.1841x; 1.0275x over previous
#include <cuda_runtime.h>
#include <cuda_bf16.h>
#include <math_constants.h>
#include <cstdint>

// Problem constants (fixed shapes)
#define BATCH 8
#define LSEQ 4096
#define DDIM 1024
#define SMEM_ROWS 256      // S
#define NG 3               // ngram order
#define M_TOTAL (BATCH*LSEQ)   // 32768
#define NROWS (M_TOTAL*NG)     // 98304 (m,n) rows

// GEMM tiling (mma.sync bf16, family-compatible PTX)
#define TILE_M 128
#define TILE_N 128          // half of S per block
#define KSTAGE 64           // bf16 k per stage (128 B rows, SW128)
#define NK (DDIM / KSTAGE)  // 16 k-stages
#define STAGES 3
#define STAGE_A_BYTES (TILE_M * KSTAGE * 2)   // 16384
#define STAGE_BYTES (2 * STAGE_A_BYTES)        // 32768 (A + B)
#define SMEM_DYN (STAGES * STAGE_BYTES)        // 98304

#define MARGIN 1.0f
#define MAXC 8              // candidates per 64-col chunk
#define MAXCAND 32          // 4 chunks x MAXC
#define OVF_SENT 255        // slot sentinel: scan 32 s from cand[0]

// cvt/score overlap split
#define X_IT8  (M_TOTAL * DDIM / 8)          // 4,194,304 8-float items
#define MEM_IT8 (SMEM_ROWS * NG * DDIM / 8)  //   98,304
#define X8_PER_ROW (DDIM / 8)                // 128
#define YSPLIT 64                            // m-tiles in early score launch
#define X8_SPLIT (YSPLIT * TILE_M * X8_PER_ROW)  // first 8192 rows

// ---------------------------------------------------------------------------
// Scratch (device globals; no cudaMalloc allowed)
// ---------------------------------------------------------------------------
__device__ __align__(128) __nv_bfloat16 g_xbf[(size_t)M_TOTAL * DDIM];      // 64 MB
__device__ __align__(128) __nv_bfloat16 g_membf[(size_t)SMEM_ROWS * NG * DDIM];
__device__ unsigned long long g_bestpack[NROWS];   // (key<<32)|(255-s)
__device__ int   g_pad_best[NG];
__device__ float g_cmax[(size_t)NROWS * 4];        // per-chunk max
__device__ int   g_ccnt[(size_t)NROWS * 4];        // per-chunk candidate count
__device__ int   g_cidx2[(size_t)NROWS * 4 * MAXC];
__device__ float g_csc[(size_t)NROWS * 4 * MAXC];
__device__ int   g_row_cnt;
__device__ int   g_rrow[NROWS];                    // ambiguous-row worklist
__device__ int   g_rnc[NROWS];                     // candidate count (or OVF_SENT)
__device__ int   g_rcand[(size_t)NROWS * MAXCAND];

// ---------------------------------------------------------------------------
// Family-safe PTX helpers (cp.async / ldmatrix / mma.sync only)
// ---------------------------------------------------------------------------
__device__ __forceinline__ uint32_t smem_u32(const void* p) {
    uint32_t a;
    asm("{ .reg .u64 t; cvta.to.shared.u64 t, %1; cvt.u32.u64 %0, t; }" : "=r"(a) : "l"(p));
    return a;
}
__device__ __forceinline__ void cp_async16(uint32_t dst, const void* src) {
    asm volatile("cp.async.cg.shared.global [%0], [%1], 16;" :: "r"(dst), "l"(src));
}
#define CP_COMMIT() asm volatile("cp.async.commit_group;" ::: "memory")
#define CP_WAIT(N)  asm volatile("cp.async.wait_group %0;" :: "n"(N) : "memory")

__device__ __forceinline__ void ldmx4(uint32_t* r, uint32_t addr) {
    asm volatile("ldmatrix.sync.aligned.m8n8.x4.shared.b16 {%0,%1,%2,%3}, [%4];"
                 : "=r"(r[0]), "=r"(r[1]), "=r"(r[2]), "=r"(r[3]) : "r"(addr));
}
__device__ __forceinline__ void mma16816(float* c, const uint32_t* a,
                                         uint32_t b0, uint32_t b1) {
    asm volatile(
        "mma.sync.aligned.m16n8k16.row.col.f32.bf16.bf16.f32 "
        "{%0,%1,%2,%3}, {%4,%5,%6,%7}, {%8,%9}, {%0,%1,%2,%3};"
        : "+f"(c[0]), "+f"(c[1]), "+f"(c[2]), "+f"(c[3])
        : "r"(a[0]), "r"(a[1]), "r"(a[2]), "r"(a[3]), "r"(b0), "r"(b1));
}

// SW128 xor swizzle for 128-byte rows: g (16B group 0..7) xored with row&7
__device__ __forceinline__ uint32_t swz128(int row, int g) {
    return (uint32_t)(row * 128 + ((g ^ (row & 7)) << 4));
}

// Pack two floats to bf16x2 (lo = first arg, per __floats2bfloat162_rn contract)
__device__ __forceinline__ uint32_t pack_bf16x2(float lo, float hi) {
    __nv_bfloat162 h = __floats2bfloat162_rn(lo, hi);
    return *reinterpret_cast<uint32_t*>(&h);
}

// Monotonic float->u32 key (order-preserving for all finite floats)
__device__ __forceinline__ uint32_t fkey(float v) {
    uint32_t u = __float_as_uint(v);
    return (u & 0x80000000u) ? ~u : (u | 0x80000000u);
}
// Winner pack: larger score wins; on equal score, lower s wins (255-s larger)
__device__ __forceinline__ unsigned long long wpack(float v, int s) {
    return ((unsigned long long)fkey(v) << 32) | (unsigned long long)(255 - s);
}
__device__ __forceinline__ int wdecode(unsigned long long p) {
    return 255 - (int)(p & 0xffull);
}

// ---------------------------------------------------------------------------
// Range conversion fp32 -> bf16. Phase with with_mem=1 also converts the
// memory table, computes pad-bias argmax, and resets the worklist counter.
// ---------------------------------------------------------------------------
__global__ void cvt_part_kernel(const float4* __restrict__ x,
                                const float4* __restrict__ mem,
                                const float* __restrict__ pb,
                                int x8_begin, int x8_end, int with_mem)
{
    if (with_mem && blockIdx.x == 0 && threadIdx.x == 0) g_row_cnt = 0;

    uint4* xo = reinterpret_cast<uint4*>(g_xbf);
    uint4* mo = reinterpret_cast<uint4*>(g_membf);
    const int xcount = x8_end - x8_begin;
    const int total = xcount + (with_mem ? MEM_IT8 : 0);
    for (int i = blockIdx.x * blockDim.x + threadIdx.x; i < total;
         i += gridDim.x * blockDim.x) {
        const float4* src; uint4* dst; int j;
        if (i < xcount) { src = x;  dst = xo; j = x8_begin + i; }
        else            { src = mem; dst = mo; j = i - xcount; }
        float4 a = src[2 * j], b = src[2 * j + 1];
        uint4 o;
        o.x = pack_bf16x2(a.x, a.y);
        o.y = pack_bf16x2(a.z, a.w);
        o.z = pack_bf16x2(b.x, b.y);
        o.w = pack_bf16x2(b.z, b.w);
        dst[j] = o;
    }

    // pad-bias argmax, block 0 only (96 working threads, uniform sync)
    if (with_mem && blockIdx.x == 0) {
        __shared__ float sv[96];
        __shared__ int   si[96];
        int t = threadIdx.x;
        if (t < 96) {
            int n = t % NG, q = t / NG;
            float bv = -CUDART_INF_F; int bi = 0;
            for (int s = q; s < SMEM_ROWS; s += 32) {
                float v = pb[s * NG + n];
                if (v > bv || (v == bv && s < bi)) { bv = v; bi = s; }
            }
            sv[t] = bv; si[t] = bi;
        }
        __syncthreads();
        if (t < NG) {
            float bv = -CUDART_INF_F; int bi = 0;
            for (int j = 0; j < 32; j++) {
                float v = sv[t + j * NG]; int s = si[t + j * NG];
                if (v > bv || (v == bv && s < bi)) { bv = v; bi = s; }
            }
            g_pad_best[t] = bi;
        }
    }
}

// ---------------------------------------------------------------------------
// Score GEMM (bf16 mma.sync, fp32 accum) + fused max/candidate epilogue.
// grid (6, Ny): cx -> n = cx>>1, s-half = cx&1; y + y0 = m-tile.
// 3-stage pipeline, ONE sync per k-iter.
// ---------------------------------------------------------------------------
__global__ __launch_bounds__(128, 2)
void score_mma_kernel(const float* __restrict__ pb, int y0)
{
    extern __shared__ __align__(128) char dynsm[];
    __shared__ float pbias_sm[TILE_N];

    const int tid  = threadIdx.x;
    const int wid  = tid >> 5;
    const int lane = tid & 31;
    const int wm   = wid & 1;          // warp m (0/1): rows 64*wm
    const int wn   = wid >> 1;         // warp n (0/1): cols 64*wn
    const int cx   = blockIdx.x;       // 0..5
    const int n    = cx >> 1;
    const int half = cx & 1;
    const int s0   = half * TILE_N;    // global S offset of this block
    const int m0   = (blockIdx.y + y0) * TILE_M;

    const uint32_t sbase = smem_u32(dynsm);
    const __nv_bfloat16* __restrict__ xbf = g_xbf;
    const __nv_bfloat16* __restrict__ mbf = g_membf;

    for (int i = tid; i < TILE_N; i += 128)
        pbias_sm[i] = pb[(s0 + i) * NG + n];

    // ---- cp.async stage issue: 2048 x 16B chunks (A 1024 + B 1024) ----
    auto issue_stage = [&](int st) {
        const int k0 = st * KSTAGE;
        const uint32_t ab = sbase + (st % STAGES) * STAGE_BYTES;
        const uint32_t bb = ab + STAGE_A_BYTES;
        #pragma unroll
        for (int q = 0; q < 16; q++) {
            int c = tid + q * 128;              // 0..2047
            if (q < 8) {
                int row = c >> 3, g = c & 7;
                cp_async16(ab + swz128(row, g),
                           xbf + (size_t)(m0 + row) * DDIM + k0 + g * 8);
            } else {
                int cc = c - 1024;
                int row = cc >> 3, g = cc & 7;
                cp_async16(bb + swz128(row, g),
                           mbf + ((size_t)(s0 + row) * NG + n) * DDIM + k0 + g * 8);
            }
        }
    };

    issue_stage(0); CP_COMMIT();
    issue_stage(1); CP_COMMIT();

    float acc[4][8][4];
    #pragma unroll
    for (int i = 0; i < 4; i++)
        #pragma unroll
        for (int j = 0; j < 8; j++)
            #pragma unroll
            for (int c = 0; c < 4; c++) acc[i][j][c] = 0.0f;

    for (int ks = 0; ks < NK; ks++) {
        CP_WAIT(1);            // stage ks complete (only ks+1 may be pending)
        __syncthreads();       // all warps done computing ks-1 -> its buffer free

        if (ks + 2 < NK) issue_stage(ks + 2);   // fills buffer (ks+2)%3 == (ks-1)%3
        CP_COMMIT();

        const uint32_t ab = sbase + (ks % STAGES) * STAGE_BYTES;
        const uint32_t bb = ab + STAGE_A_BYTES;
        #pragma unroll
        for (int t = 0; t < 4; t++) {          // 4 x k16 within the stage
            uint32_t ar[4][4];
            #pragma unroll
            for (int i = 0; i < 4; i++)
                ldmx4(ar[i], ab + swz128(wm * 64 + i * 16 + (lane & 15),
                                         t * 2 + (lane >> 4)));
            #pragma unroll
            for (int j2 = 0; j2 < 4; j2++) {
                uint32_t br[4];
                ldmx4(br, bb + swz128(wn * 64 + j2 * 16 + (lane & 15),
                                      t * 2 + (lane >> 4)));
                #pragma unroll
                for (int i = 0; i < 4; i++) {
                    mma16816(acc[i][2 * j2 + 0], ar[i], br[0], br[2]);
                    mma16816(acc[i][2 * j2 + 1], ar[i], br[1], br[3]);
                }
            }
        }
    }

    // ---- Epilogue: per-row max + candidates for this warp's 64-col chunk ----
    const int grp = lane >> 2;     // 0..7 row-in-frag
    const int qc  = lane & 3;      // col quad
    const int chunk = half * 2 + wn;
    const unsigned FULL = 0xffffffffu;

    #pragma unroll
    for (int i = 0; i < 4; i++) {
        #pragma unroll
        for (int h = 0; h < 2; h++) {
            const int m = m0 + wm * 64 + i * 16 + h * 8 + grp;
            float vals[16];
            float mx = -CUDART_INF_F;
            #pragma unroll
            for (int j = 0; j < 8; j++) {
                #pragma unroll
                for (int c = 0; c < 2; c++) {
                    int col = wn * 64 + j * 8 + qc * 2 + c;   // local 0..127
                    float v = acc[i][j][h * 2 + c] + pbias_sm[col];
                    vals[j * 2 + c] = v;
                    mx = fmaxf(mx, v);
                }
            }
            mx = fmaxf(mx, __shfl_xor_sync(FULL, mx, 1));
            mx = fmaxf(mx, __shfl_xor_sync(FULL, mx, 2));
            const float thr = mx - MARGIN;

            int   lidx[16]; float lsc[16]; int lc = 0;
            #pragma unroll
            for (int t = 0; t < 16; t++) {
                if (vals[t] > thr) {
                    lidx[lc] = s0 + wn * 64 + (t >> 1) * 8 + qc * 2 + (t & 1);
                    lsc[lc]  = vals[t];
                    lc++;
                }
            }
            int b4 = lane & ~3;
            int c0 = __shfl_sync(FULL, lc, b4 + 0);
            int c1 = __shfl_sync(FULL, lc, b4 + 1);
            int c2 = __shfl_sync(FULL, lc, b4 + 2);
            int c3 = __shfl_sync(FULL, lc, b4 + 3);
            int total = c0 + c1 + c2 + c3;
            int off0  = (qc > 0 ? c0 : 0) + (qc > 1 ? c1 : 0) + (qc > 2 ? c2 : 0);

            size_t ridx = (size_t)m * NG + n;
            size_t cbase = (ridx * 4 + chunk) * MAXC;
            for (int t = 0; t < lc; t++) {
                int p = off0 + t;
                if (p < MAXC) { g_cidx2[cbase + p] = lidx[t]; g_csc[cbase + p] = lsc[t]; }
            }
            if (qc == 0) {
                g_cmax[ridx * 4 + chunk] = mx;
                g_ccnt[ridx * 4 + chunk] = total;
            }
        }
    }
}

// ---------------------------------------------------------------------------
// Refine plan: decide nc==1 rows; push one worklist slot per ambiguous row.
// Overflow rows: bestpack=0 + 8 sub-range slots (atomicMax merge in exec).
// ---------------------------------------------------------------------------
__global__ __launch_bounds__(256)
void refine_plan_kernel()
{
    int idx = blockIdx.x * blockDim.x + threadIdx.x;
    if (idx >= NROWS) return;

    float gmax = -CUDART_INF_F;
    bool ovf = false;
    int cc[4];
    #pragma unroll
    for (int ch = 0; ch < 4; ch++) {
        float v = g_cmax[(size_t)idx * 4 + ch];
        cc[ch] = g_ccnt[(size_t)idx * 4 + ch];
        if (v > gmax) gmax = v;
        if (cc[ch] > MAXC) ovf = true;
    }
    const float thr = gmax - MARGIN;

    if (!ovf) {
        int cand[MAXCAND]; int nc = 0;
        #pragma unroll
        for (int ch = 0; ch < 4; ch++) {
            size_t cb = ((size_t)idx * 4 + ch) * MAXC;
            for (int p = 0; p < cc[ch]; p++) {
                if (g_csc[cb + p] > thr) cand[nc++] = g_cidx2[cb + p];
            }
        }
        if (nc == 1) {
            g_bestpack[idx] = wpack(0.0f, cand[0]);   // decided; key irrelevant
            return;
        }
        int slot = atomicAdd(&g_row_cnt, 1);
        g_rrow[slot] = idx;
        g_rnc[slot]  = nc;
        for (int c = 0; c < nc; c++) g_rcand[(size_t)slot * MAXCAND + c] = cand[c];
    } else {
        g_bestpack[idx] = 0ull;     // atomicMax target
        int base = atomicAdd(&g_row_cnt, 8);
        for (int q = 0; q < 8; q++) {
            g_rrow[base + q] = idx;
            g_rnc[base + q]  = OVF_SENT;
            g_rcand[(size_t)(base + q) * MAXCAND] = q * 32;   // s range start
        }
    }
}

// ---------------------------------------------------------------------------
// Refine exec: one WARP per worklist slot. Coalesced lane mapping (lane l owns
// float4 indices l + 32k). x row cached in regs, reused across candidates.
// Exact fp32 dot + xor-butterfly reduction; winner via order-independent
// compare (v, then lower s).
// ---------------------------------------------------------------------------
__global__ __launch_bounds__(256)
void refine_exec_kernel(const float* __restrict__ x,
                        const float* __restrict__ mem,
                        const float* __restrict__ pb)
{
    const unsigned FULL = 0xffffffffu;
    const int total = g_row_cnt;
    const int lane = threadIdx.x & 31;
    const int gw   = (blockIdx.x * blockDim.x + threadIdx.x) >> 5;
    const int nw   = (gridDim.x * blockDim.x) >> 5;

    for (int slot = gw; slot < total; slot += nw) {
        const int idx = g_rrow[slot];
        const int nc  = g_rnc[slot];
        const int m = idx / NG;
        const int n = idx - m * NG;

        // Coalesced x-row load into registers: lane l takes float4 l + 32k
        const float4* xr = reinterpret_cast<const float4*>(x + (size_t)m * DDIM);
        float4 ax[8];
        #pragma unroll
        for (int k = 0; k < 8; k++) ax[k] = xr[lane + 32 * k];

        const int count = (nc == OVF_SENT) ? 32 : nc;
        const int sbase = (nc == OVF_SENT) ? g_rcand[(size_t)slot * MAXCAND] : 0;

        float bestv = -CUDART_INF_F; int besti = SMEM_ROWS;
        for (int c = 0; c < count; c++) {
            const int s = (nc == OVF_SENT) ? (sbase + c)
                                           : g_rcand[(size_t)slot * MAXCAND + c];
            const float4* mr = reinterpret_cast<const float4*>(
                mem + ((size_t)s * NG + n) * DDIM);
            float acc = 0.0f;
            #pragma unroll
            for (int k = 0; k < 8; k++) {
                float4 b = mr[lane + 32 * k];
                acc = fmaf(ax[k].x, b.x, acc);
                acc = fmaf(ax[k].y, b.y, acc);
                acc = fmaf(ax[k].z, b.z, acc);
                acc = fmaf(ax[k].w, b.w, acc);
            }
            #pragma unroll
            for (int off = 16; off >= 1; off >>= 1)
                acc += __shfl_xor_sync(FULL, acc, off);

            if (lane == 0) {
                float v = acc + pb[s * NG + n];
                if (v > bestv || (v == bestv && s < besti)) { bestv = v; besti = s; }
            }
        }
        if (lane == 0) {
            if (nc == OVF_SENT) atomicMax(&g_bestpack[idx], wpack(bestv, besti));
            else                g_bestpack[idx] = wpack(0.0f, besti);
        }
    }
}

// ---------------------------------------------------------------------------
// Gather + sum: out[b,l,:] = sum_n memory[best_n(b, l+n-2), n, :]
// TWO rows per loop iteration (m and m+gridDim.x) -> 6 independent index
// loads + 6 row loads + 2 stores per iter: doubles MLP on the latency chain.
// ---------------------------------------------------------------------------
__global__ __launch_bounds__(256)
void gather_kernel(const float* __restrict__ mem, float* __restrict__ out)
{
    const int d = threadIdx.x;
    const int stride = gridDim.x;
    for (int m = blockIdx.x; m < M_TOTAL; m += 2 * stride) {
        const int mA = m;
        const int mB = m + stride;          // M_TOTAL/stride is even -> in range
        const int lA = mA & (LSEQ - 1);
        const int lB = mB & (LSEQ - 1);

        int a0 = (lA - 2 < 0) ? g_pad_best[0] : wdecode(g_bestpack[(size_t)(mA - 2) * NG + 0]);
        int a1 = (lA - 1 < 0) ? g_pad_best[1] : wdecode(g_bestpack[(size_t)(mA - 1) * NG + 1]);
        int a2 = wdecode(g_bestpack[(size_t)mA * NG + 2]);
        int b0 = (lB - 2 < 0) ? g_pad_best[0] : wdecode(g_bestpack[(size_t)(mB - 2) * NG + 0]);
        int b1 = (lB - 1 < 0) ? g_pad_best[1] : wdecode(g_bestpack[(size_t)(mB - 1) * NG + 1]);
        int b2 = wdecode(g_bestpack[(size_t)mB * NG + 2]);

        const float4* ra0 = reinterpret_cast<const float4*>(mem + ((size_t)a0 * NG + 0) * DDIM);
        const float4* ra1 = reinterpret_cast<const float4*>(mem + ((size_t)a1 * NG + 1) * DDIM);
        const float4* ra2 = reinterpret_cast<const float4*>(mem + ((size_t)a2 * NG + 2) * DDIM);
        const float4* rb0 = reinterpret_cast<const float4*>(mem + ((size_t)b0 * NG + 0) * DDIM);
        const float4* rb1 = reinterpret_cast<const float4*>(mem + ((size_t)b1 * NG + 1) * DDIM);
        const float4* rb2 = reinterpret_cast<const float4*>(mem + ((size_t)b2 * NG + 2) * DDIM);

        float4 va0 = ra0[d], va1 = ra1[d], va2 = ra2[d];
        float4 vb0 = rb0[d], vb1 = rb1[d], vb2 = rb2[d];

        float4 sa, sb;
        sa.x = (va0.x + va1.x) + va2.x;
        sa.y = (va0.y + va1.y) + va2.y;
        sa.z = (va0.z + va1.z) + va2.z;
        sa.w = (va0.w + va1.w) + va2.w;
        sb.x = (vb0.x + vb1.x) + vb2.x;
        sb.y = (vb0.y + vb1.y) + vb2.y;
        sb.z = (vb0.z + vb1.z) + vb2.z;
        sb.w = (vb0.w + vb1.w) + vb2.w;

        reinterpret_cast<float4*>(out + (size_t)mA * DDIM)[d] = sa;
        reinterpret_cast<float4*>(out + (size_t)mB * DDIM)[d] = sb;
    }
}

// ---------------------------------------------------------------------------
extern "C" void kernel_launch(void* const* d_in, const int* in_sizes, int n_in,
                              void* d_out, int out_size)
{
    const float* x   = (const float*)d_in[0];   // (8, 4096, 1024) f32
    const float* mem = (const float*)d_in[1];   // (256, 3, 1024) f32
    const float* pb  = (const float*)d_in[2];   // (256, 3) f32
    float* out = (float*)d_out;                 // (8, 4096, 1024) f32

    // One-time side stream + events (created outside capture on the
    // correctness run; reused during graph capture). No device memory.
    static cudaStream_t s2 = nullptr;
    static cudaEvent_t e0 = nullptr, e1 = nullptr;
    if (!s2) {
        cudaStreamCreateWithFlags(&s2, cudaStreamNonBlocking);
        cudaEventCreateWithFlags(&e0, cudaEventDisableTiming);
        cudaEventCreateWithFlags(&e1, cudaEventDisableTiming);
    }

    cudaFuncSetAttribute(score_mma_kernel,
                         cudaFuncAttributeMaxDynamicSharedMemorySize, SMEM_DYN);

    // Phase 0: mem table + pad bias + first YSPLIT m-tiles of x
    cvt_part_kernel<<<1024, 256>>>((const float4*)x, (const float4*)mem, pb,
                                   0, X8_SPLIT, 1);
    cudaEventRecord(e0, 0);

    // Side stream: score over the early m-tiles (overlaps remaining cvt)
    cudaStreamWaitEvent(s2, e0, 0);
    {
        dim3 gridA(6, YSPLIT);
        score_mma_kernel<<<gridA, 128, SMEM_DYN, s2>>>(pb, 0);
    }
    cudaEventRecord(e1, s2);

    // Main: convert remaining x rows, then score the remaining m-tiles
    cvt_part_kernel<<<2048, 256>>>((const float4*)x, (const float4*)mem, pb,
                                   X8_SPLIT, X_IT8, 0);
    {
        dim3 gridB(6, 256 - YSPLIT);
        score_mma_kernel<<<gridB, 128, SMEM_DYN>>>(pb, YSPLIT);
    }

    // Join side stream before consuming score results
    cudaStreamWaitEvent(0, e1, 0);

    refine_plan_kernel<<<(NROWS + 255) / 256, 256>>>();
    refine_exec_kernel<<<1024, 256>>>(x, mem, pb);
    gather_kernel<<<2048, 256>>>(mem, out);
}